// round 3
// baseline (speedup 1.0000x reference)
#include <cuda_runtime.h>
#include <cstddef>

#define NSEQ   4096
#define BATCH  8
#define DMODEL 512
#define HEADS  8
#define RRANK  256
#define DEPTH  64
#define MROWS  32768          // BATCH*NSEQ
#define NCHUNK 8

// ---------------- scratch (static device allocations only) ----------------
__device__ float g_q[16777216];      // 32768 x 512
__device__ float g_k[16777216];
__device__ float g_v[16777216];
__device__ float g_part[8388608];    // NCHUNK x (64*256*64)
__device__ float g_kp[1048576];      // [B*H, 256, 64]
__device__ float g_vp[1048576];
__device__ float g_cat[16777216];    // attention output, concat layout

// ---------------- SGEMM: C[M,Nn] = A[M,K] @ B[K,Nn] (+bias) ----------------
// BM=128, BN=128, BK=16, 256 threads, 8x8 per-thread microtile.
__global__ void sgemm_bias(const float* __restrict__ A, const float* __restrict__ B,
                           const float* __restrict__ bias, float* __restrict__ C,
                           int M, int K, int Nn) {
    __shared__ float As[16][128];    // transposed: As[k][m]
    __shared__ float Bs[16][128];
    const int bx = blockIdx.x;       // N tile
    const int by = blockIdx.y;       // M tile
    const int tid = threadIdx.x;
    const int tx = tid & 15;         // col tile
    const int ty = tid >> 4;         // row tile

    const float* Ab = A + (size_t)by * 128 * K;
    const float* Bb = B + bx * 128;

    float acc[8][8];
#pragma unroll
    for (int i = 0; i < 8; i++)
#pragma unroll
        for (int j = 0; j < 8; j++) acc[i][j] = 0.f;

    const int aRow = tid >> 2;          // 0..63
    const int aCol = (tid & 3) * 4;     // 0,4,8,12
    const int bRow = tid >> 5;          // 0..7
    const int bCol = (tid & 31) * 4;    // 0..124

    for (int k0 = 0; k0 < K; k0 += 16) {
#pragma unroll
        for (int rr = 0; rr < 2; rr++) {
            int r = aRow + rr * 64;
            float4 av = *(const float4*)(Ab + (size_t)r * K + k0 + aCol);
            As[aCol + 0][r] = av.x; As[aCol + 1][r] = av.y;
            As[aCol + 2][r] = av.z; As[aCol + 3][r] = av.w;
        }
#pragma unroll
        for (int rr = 0; rr < 2; rr++) {
            int r = bRow + rr * 8;
            *(float4*)&Bs[r][bCol] = *(const float4*)(Bb + (size_t)(k0 + r) * Nn + bCol);
        }
        __syncthreads();
#pragma unroll
        for (int kk = 0; kk < 16; kk++) {
            float ra[8], rb[8];
            *(float4*)&ra[0] = *(const float4*)&As[kk][ty * 8];
            *(float4*)&ra[4] = *(const float4*)&As[kk][ty * 8 + 4];
            *(float4*)&rb[0] = *(const float4*)&Bs[kk][tx * 8];
            *(float4*)&rb[4] = *(const float4*)&Bs[kk][tx * 8 + 4];
#pragma unroll
            for (int i = 0; i < 8; i++)
#pragma unroll
                for (int j = 0; j < 8; j++)
                    acc[i][j] = fmaf(ra[i], rb[j], acc[i][j]);
        }
        __syncthreads();
    }

    float* Cb = C + (size_t)by * 128 * Nn + bx * 128;
#pragma unroll
    for (int i = 0; i < 8; i++) {
        int r = ty * 8 + i;
#pragma unroll
        for (int j = 0; j < 8; j += 4) {
            int c = tx * 8 + j;
            float4 o;
            o.x = acc[i][j + 0]; o.y = acc[i][j + 1];
            o.z = acc[i][j + 2]; o.w = acc[i][j + 3];
            if (bias) {
                o.x += bias[bx * 128 + c + 0]; o.y += bias[bx * 128 + c + 1];
                o.z += bias[bx * 128 + c + 2]; o.w += bias[bx * 128 + c + 3];
            }
            *(float4*)(Cb + (size_t)r * Nn + c) = o;
        }
    }
}

// ---------------- Projection: partial[chunk][bh][r][dep] = sum_{n in chunk} P[h,n,r]*src[b,n,h*64+dep]
// grid (B*H, NCHUNK), 256 threads; thread owns r = tid, accumulates all 64 deps.
__global__ void proj_kernel(const float* __restrict__ src, const float* __restrict__ P,
                            float* __restrict__ partial) {
    __shared__ float Es[32 * 256];      // 32 KB
    __shared__ float Ks[32 * 68];       // 8.5 KB (padded stride 68, float4-aligned)
    const int bh = blockIdx.x;
    const int b = bh >> 3, h = bh & 7;
    const int chunk = blockIdx.y;
    const int tid = threadIdx.x;

    float acc[64];
#pragma unroll
    for (int d = 0; d < 64; d++) acc[d] = 0.f;

    const float* Pb = P + (size_t)h * NSEQ * RRANK;
    const float* Sb = src + (size_t)b * NSEQ * DMODEL + h * DEPTH;
    const int nbeg = chunk * (NSEQ / NCHUNK);

    for (int n0 = nbeg; n0 < nbeg + NSEQ / NCHUNK; n0 += 32) {
#pragma unroll 8
        for (int nn = 0; nn < 32; nn++)
            Es[nn * 256 + tid] = Pb[(size_t)(n0 + nn) * RRANK + tid];
#pragma unroll
        for (int i = 0; i < 8; i++) {
            int idx = i * 256 + tid;
            int nn = idx >> 6, dep = idx & 63;
            Ks[nn * 68 + dep] = Sb[(size_t)(n0 + nn) * DMODEL + dep];
        }
        __syncthreads();
        for (int nn = 0; nn < 32; nn += 2) {
            float e0 = Es[nn * 256 + tid];
            float e1 = Es[nn * 256 + 256 + tid];
#pragma unroll
            for (int d = 0; d < 64; d += 4) {
                float4 k0 = *(const float4*)&Ks[nn * 68 + d];
                float4 k1 = *(const float4*)&Ks[nn * 68 + 68 + d];
                acc[d + 0] = fmaf(e1, k1.x, fmaf(e0, k0.x, acc[d + 0]));
                acc[d + 1] = fmaf(e1, k1.y, fmaf(e0, k0.y, acc[d + 1]));
                acc[d + 2] = fmaf(e1, k1.z, fmaf(e0, k0.z, acc[d + 2]));
                acc[d + 3] = fmaf(e1, k1.w, fmaf(e0, k0.w, acc[d + 3]));
            }
        }
        __syncthreads();
    }

    float* o = partial + (size_t)chunk * (64 * 256 * 64) + ((size_t)bh * 256 + tid) * 64;
#pragma unroll
    for (int d = 0; d < 64; d += 4)
        *(float4*)&o[d] = make_float4(acc[d], acc[d + 1], acc[d + 2], acc[d + 3]);
}

// ---------------- deterministic partial reduction ----------------
__global__ void reduce_partials(const float* __restrict__ part, float* __restrict__ out) {
    int i = blockIdx.x * 256 + threadIdx.x;
    float s = 0.f;
#pragma unroll
    for (int c = 0; c < NCHUNK; c++) s += part[(size_t)c * 1048576 + i];
    out[i] = s;
}

// ---------------- fused attention: scores -> softmax -> @v_proj ----------------
// grid (NSEQ/64, B*H), 256 threads. Dynamic smem: Qs 64x65 | union(Kp 256x65, S 64x264) | Vp 256x68.
__global__ void attn_kernel(const float* __restrict__ q, const float* __restrict__ kp,
                            const float* __restrict__ vp, float* __restrict__ outc) {
    extern __shared__ float sm[];
    float* Qs  = sm;                 // 4160 floats
    float* KpS = sm + 4160;          // 16896 floats (Kp then reused as S)
    float* Vp  = sm + 21056;         // 17408 floats
    __shared__ float red[64 * 32];

    const int m0 = blockIdx.x * 64;
    const int bh = blockIdx.y;
    const int b = bh >> 3, h = bh & 7;
    const int tid = threadIdx.x;

    const float* qb = q + ((size_t)b * NSEQ + m0) * DMODEL + h * DEPTH;
#pragma unroll
    for (int i = 0; i < 16; i++) {
        int idx = i * 256 + tid;
        int m = idx >> 6, dep = idx & 63;
        Qs[m * 65 + dep] = qb[(size_t)m * DMODEL + dep] * 0.125f;   // 1/sqrt(64)
    }
    const float* kpb = kp + (size_t)bh * RRANK * DEPTH;
    const float* vpb = vp + (size_t)bh * RRANK * DEPTH;
#pragma unroll
    for (int i = 0; i < 64; i++) {
        int idx = i * 256 + tid;
        int r = idx >> 6, dep = idx & 63;
        KpS[r * 65 + dep] = kpb[idx];
        Vp[r * 68 + dep] = vpb[idx];
    }
    __syncthreads();

    // scores: 8x8 microtile. tx -> r tile (8*tx), ty -> m tile (8*ty)
    const int tx = tid & 31, ty = tid >> 5;
    float acc[8][8];
#pragma unroll
    for (int i = 0; i < 8; i++)
#pragma unroll
        for (int j = 0; j < 8; j++) acc[i][j] = 0.f;

    for (int dep = 0; dep < 64; dep++) {
        float ra[8], rb[8];
#pragma unroll
        for (int i = 0; i < 8; i++) ra[i] = Qs[(ty * 8 + i) * 65 + dep];
#pragma unroll
        for (int j = 0; j < 8; j++) rb[j] = KpS[(tx * 8 + j) * 65 + dep];
#pragma unroll
        for (int i = 0; i < 8; i++)
#pragma unroll
            for (int j = 0; j < 8; j++) acc[i][j] = fmaf(ra[i], rb[j], acc[i][j]);
    }

    // softmax over r (256) per row m
    float rowmax[8], inv[8];
#pragma unroll
    for (int i = 0; i < 8; i++) {
        float pm = acc[i][0];
#pragma unroll
        for (int j = 1; j < 8; j++) pm = fmaxf(pm, acc[i][j]);
        red[(ty * 8 + i) * 32 + tx] = pm;
    }
    __syncthreads();
#pragma unroll
    for (int i = 0; i < 8; i++) {
        float mx = red[(ty * 8 + i) * 32];
        for (int j2 = 1; j2 < 32; j2++) mx = fmaxf(mx, red[(ty * 8 + i) * 32 + j2]);
        rowmax[i] = mx;
    }
    __syncthreads();
#pragma unroll
    for (int i = 0; i < 8; i++) {
        float s = 0.f;
#pragma unroll
        for (int j = 0; j < 8; j++) {
            acc[i][j] = __expf(acc[i][j] - rowmax[i]);
            s += acc[i][j];
        }
        red[(ty * 8 + i) * 32 + tx] = s;
    }
    __syncthreads();
#pragma unroll
    for (int i = 0; i < 8; i++) {
        float s = red[(ty * 8 + i) * 32];
        for (int j2 = 1; j2 < 32; j2++) s += red[(ty * 8 + i) * 32 + j2];
        inv[i] = 1.0f / s;
    }

    // write normalized P into KpS (reused as S, stride 264). All Kp reads finished before sync #1.
#pragma unroll
    for (int i = 0; i < 8; i++) {
#pragma unroll
        for (int j = 0; j < 8; j += 4) {
            float4 pv = make_float4(acc[i][j] * inv[i], acc[i][j + 1] * inv[i],
                                    acc[i][j + 2] * inv[i], acc[i][j + 3] * inv[i]);
            *(float4*)&KpS[(ty * 8 + i) * 264 + tx * 8 + j] = pv;
        }
    }
    __syncthreads();

    // out = P @ Vp : 4x4 microtile. tx2 -> dep tile, ty2 -> m tile
    const int tx2 = tid & 15, ty2 = tid >> 4;
    float o[4][4];
#pragma unroll
    for (int i = 0; i < 4; i++)
#pragma unroll
        for (int j = 0; j < 4; j++) o[i][j] = 0.f;

    for (int r = 0; r < 256; r++) {
        float4 vv = *(const float4*)&Vp[r * 68 + tx2 * 4];
#pragma unroll
        for (int i = 0; i < 4; i++) {
            float a = KpS[(ty2 * 4 + i) * 264 + r];
            o[i][0] = fmaf(a, vv.x, o[i][0]);
            o[i][1] = fmaf(a, vv.y, o[i][1]);
            o[i][2] = fmaf(a, vv.z, o[i][2]);
            o[i][3] = fmaf(a, vv.w, o[i][3]);
        }
    }

    float* ob = outc + ((size_t)b * NSEQ + m0) * DMODEL + h * DEPTH;
#pragma unroll
    for (int i = 0; i < 4; i++)
        *(float4*)&ob[(size_t)(ty2 * 4 + i) * DMODEL + tx2 * 4] =
            make_float4(o[i][0], o[i][1], o[i][2], o[i][3]);
}

// ---------------- launch ----------------
extern "C" void kernel_launch(void* const* d_in, const int* in_sizes, int n_in,
                              void* d_out, int out_size) {
    const float* x  = (const float*)d_in[0];
    const float* wq = (const float*)d_in[1];
    const float* wk = (const float*)d_in[2];
    const float* wv = (const float*)d_in[3];
    const float* E  = (const float*)d_in[4];
    const float* F  = (const float*)d_in[5];
    const float* wd = (const float*)d_in[6];
    const float* bd = (const float*)d_in[7];
    float* out = (float*)d_out;

    float *gq, *gk, *gv, *gpart, *gkp, *gvp, *gcat;
    cudaGetSymbolAddress((void**)&gq, g_q);
    cudaGetSymbolAddress((void**)&gk, g_k);
    cudaGetSymbolAddress((void**)&gv, g_v);
    cudaGetSymbolAddress((void**)&gpart, g_part);
    cudaGetSymbolAddress((void**)&gkp, g_kp);
    cudaGetSymbolAddress((void**)&gvp, g_vp);
    cudaGetSymbolAddress((void**)&gcat, g_cat);

    dim3 gemm_grid(DMODEL / 128, MROWS / 128);   // (4, 256)
    sgemm_bias<<<gemm_grid, 256>>>(x, wq, nullptr, gq, MROWS, DMODEL, DMODEL);
    sgemm_bias<<<gemm_grid, 256>>>(x, wk, nullptr, gk, MROWS, DMODEL, DMODEL);
    sgemm_bias<<<gemm_grid, 256>>>(x, wv, nullptr, gv, MROWS, DMODEL, DMODEL);

    proj_kernel<<<dim3(BATCH * HEADS, NCHUNK), 256>>>(gk, E, gpart);
    reduce_partials<<<1048576 / 256, 256>>>(gpart, gkp);
    proj_kernel<<<dim3(BATCH * HEADS, NCHUNK), 256>>>(gv, F, gpart);
    reduce_partials<<<1048576 / 256, 256>>>(gpart, gvp);

    cudaFuncSetAttribute(attn_kernel, cudaFuncAttributeMaxDynamicSharedMemorySize, 153856);
    attn_kernel<<<dim3(NSEQ / 64, BATCH * HEADS), 256, 153856>>>(gq, gkp, gvp, gcat);

    sgemm_bias<<<gemm_grid, 256>>>(gcat, wd, bd, out, MROWS, DMODEL, DMODEL);
}

// round 4
// speedup vs baseline: 1.3719x; 1.3719x over previous
#include <cuda_runtime.h>
#include <cuda_bf16.h>
#include <cstddef>
#include <cstdint>

#define NSEQ   4096
#define BATCH  8
#define DMODEL 512
#define HEADS  8
#define RRANK  256
#define DEPTH  64
#define MROWS  32768          // BATCH*NSEQ
#define NCHUNK 8

// ---------------- scratch (static device allocations only) ----------------
__device__ float g_q[16777216];      // 32768 x 512
__device__ float g_k[16777216];
__device__ float g_v[16777216];
__device__ float g_part[8388608];    // NCHUNK x (64*256*64)
__device__ float g_kp[1048576];      // [B*H, 256, 64]
__device__ float g_vp[1048576];
__device__ float g_cat[16777216];    // attention output, concat layout

// split-bf16 operands
__device__ __nv_bfloat16 g_xhi[16777216];
__device__ __nv_bfloat16 g_xlo[16777216];
__device__ __nv_bfloat16 g_chi[16777216];
__device__ __nv_bfloat16 g_clo[16777216];
__device__ __nv_bfloat16 g_whi[4 * 262144];   // wq|wk|wv|wd
__device__ __nv_bfloat16 g_wlo[4 * 262144];

// ---------------- fp32 -> bf16 hi/lo split ----------------
__global__ void cvt_split(const float* __restrict__ in, __nv_bfloat16* __restrict__ hi,
                          __nv_bfloat16* __restrict__ lo, int n) {
    int i = blockIdx.x * 256 + threadIdx.x;
    if (i < n) {
        float v = in[i];
        __nv_bfloat16 h = __float2bfloat16(v);
        float r = v - __bfloat162float(h);
        hi[i] = h;
        lo[i] = __float2bfloat16(r);
    }
}

// ---------------- mma helpers ----------------
__device__ __forceinline__ void ldsm4(uint32_t r[4], const void* p) {
    uint32_t a = (uint32_t)__cvta_generic_to_shared(p);
    asm volatile("ldmatrix.sync.aligned.m8n8.x4.shared.b16 {%0,%1,%2,%3}, [%4];"
                 : "=r"(r[0]), "=r"(r[1]), "=r"(r[2]), "=r"(r[3]) : "r"(a));
}
__device__ __forceinline__ void ldsm4t(uint32_t r[4], const void* p) {
    uint32_t a = (uint32_t)__cvta_generic_to_shared(p);
    asm volatile("ldmatrix.sync.aligned.m8n8.x4.trans.shared.b16 {%0,%1,%2,%3}, [%4];"
                 : "=r"(r[0]), "=r"(r[1]), "=r"(r[2]), "=r"(r[3]) : "r"(a));
}
__device__ __forceinline__ void mma16816(float c[4], const uint32_t a[4],
                                         uint32_t b0, uint32_t b1) {
    asm volatile("mma.sync.aligned.m16n8k16.row.col.f32.bf16.bf16.f32 "
                 "{%0,%1,%2,%3},{%4,%5,%6,%7},{%8,%9},{%0,%1,%2,%3};"
                 : "+f"(c[0]), "+f"(c[1]), "+f"(c[2]), "+f"(c[3])
                 : "r"(a[0]), "r"(a[1]), "r"(a[2]), "r"(a[3]), "r"(b0), "r"(b1));
}

// ---------------- tensor-core GEMM: C = (Ahi+Alo)@(Bhi+Blo) approx, fp32 accum ----
// C = Ahi@Bhi + Ahi@Blo + Alo@Bhi   (Alo@Blo ~ 2^-16 dropped)
// BM=128, BN=128, BK=32, 256 threads = 8 warps (2x4), warp tile 64x32.
__global__ __launch_bounds__(256, 2)
void mma_gemm(const __nv_bfloat16* __restrict__ Ahi_, const __nv_bfloat16* __restrict__ Alo_,
              const __nv_bfloat16* __restrict__ Bhi_, const __nv_bfloat16* __restrict__ Blo_,
              const float* __restrict__ bias, float* __restrict__ C,
              int M, int K, int Nn) {
    __shared__ __align__(16) __nv_bfloat16 sAh[128 * 40];   // row stride 40 halves (80B)
    __shared__ __align__(16) __nv_bfloat16 sAl[128 * 40];
    __shared__ __align__(16) __nv_bfloat16 sBh[32 * 136];   // row stride 136 halves (272B)
    __shared__ __align__(16) __nv_bfloat16 sBl[32 * 136];

    const int tid  = threadIdx.x;
    const int lane = tid & 31, warp = tid >> 5;
    const int wm = (warp >> 2) * 64;     // warp m offset within block (0,64)
    const int wn = (warp & 3) * 32;      // warp n offset within block (0..96)
    const int bRow = blockIdx.y * 128, bCol = blockIdx.x * 128;

    float acc[4][4][4];
#pragma unroll
    for (int i = 0; i < 4; i++)
#pragma unroll
        for (int j = 0; j < 4; j++)
#pragma unroll
            for (int c = 0; c < 4; c++) acc[i][j][c] = 0.f;

    const int arow = tid >> 2, acol = (tid & 3) * 8;   // A: 128 rows x 32 halves
    const int brow = tid >> 4, bcol = (tid & 15) * 8;  // B: 32 rows x 128 halves

    for (int kt = 0; kt < K; kt += 32) {
#pragma unroll
        for (int rr = 0; rr < 2; rr++) {
            int r = arow + rr * 64;
            size_t go = (size_t)(bRow + r) * K + kt + acol;
            *(uint4*)&sAh[r * 40 + acol] = *(const uint4*)(Ahi_ + go);
            *(uint4*)&sAl[r * 40 + acol] = *(const uint4*)(Alo_ + go);
        }
#pragma unroll
        for (int rr = 0; rr < 2; rr++) {
            int r = brow + rr * 16;
            size_t go = (size_t)(kt + r) * Nn + bCol + bcol;
            *(uint4*)&sBh[r * 136 + bcol] = *(const uint4*)(Bhi_ + go);
            *(uint4*)&sBl[r * 136 + bcol] = *(const uint4*)(Blo_ + go);
        }
        __syncthreads();

#pragma unroll
        for (int ks = 0; ks < 2; ks++) {
            uint32_t ah[4][4], al[4][4];
            const int ar = wm + (lane & 15);
            const int ac = ks * 16 + (lane >> 4) * 8;
#pragma unroll
            for (int mi = 0; mi < 4; mi++) {
                ldsm4(ah[mi], &sAh[(ar + mi * 16) * 40 + ac]);
                ldsm4(al[mi], &sAl[(ar + mi * 16) * 40 + ac]);
            }
            const int br = ks * 16 + (lane & 15);
#pragma unroll
            for (int jp = 0; jp < 2; jp++) {       // pair of n8 fragments
                uint32_t bh[4], bl[4];
                const int bc = wn + jp * 16 + (lane >> 4) * 8;
                ldsm4t(bh, &sBh[br * 136 + bc]);
                ldsm4t(bl, &sBl[br * 136 + bc]);
#pragma unroll
                for (int h = 0; h < 2; h++) {       // n8 index = jp*2+h
#pragma unroll
                    for (int mi = 0; mi < 4; mi++) {
                        float* a4 = acc[mi][jp * 2 + h];
                        mma16816(a4, ah[mi], bh[h * 2], bh[h * 2 + 1]);
                        mma16816(a4, ah[mi], bl[h * 2], bl[h * 2 + 1]);
                        mma16816(a4, al[mi], bh[h * 2], bh[h * 2 + 1]);
                    }
                }
            }
        }
        __syncthreads();
    }

    // epilogue: c0,c1 -> (row, col..col+1); c2,c3 -> (row+8, col..col+1)
    const int gid = lane >> 2, qid = lane & 3;
#pragma unroll
    for (int mi = 0; mi < 4; mi++) {
        const int row = bRow + wm + mi * 16 + gid;
#pragma unroll
        for (int nj = 0; nj < 4; nj++) {
            const int col = bCol + wn + nj * 8 + qid * 2;
            float b0 = 0.f, b1 = 0.f;
            if (bias) { b0 = bias[col]; b1 = bias[col + 1]; }
            float2 o0 = make_float2(acc[mi][nj][0] + b0, acc[mi][nj][1] + b1);
            float2 o1 = make_float2(acc[mi][nj][2] + b0, acc[mi][nj][3] + b1);
            *(float2*)&C[(size_t)row * Nn + col] = o0;
            *(float2*)&C[(size_t)(row + 8) * Nn + col] = o1;
        }
    }
}

// ---------------- Projection: partial[chunk][bh][r][dep] ----------------
__global__ void proj_kernel(const float* __restrict__ src, const float* __restrict__ P,
                            float* __restrict__ partial) {
    __shared__ float Es[32 * 256];
    __shared__ float Ks[32 * 68];
    const int bh = blockIdx.x;
    const int b = bh >> 3, h = bh & 7;
    const int chunk = blockIdx.y;
    const int tid = threadIdx.x;

    float acc[64];
#pragma unroll
    for (int d = 0; d < 64; d++) acc[d] = 0.f;

    const float* Pb = P + (size_t)h * NSEQ * RRANK;
    const float* Sb = src + (size_t)b * NSEQ * DMODEL + h * DEPTH;
    const int nbeg = chunk * (NSEQ / NCHUNK);

    for (int n0 = nbeg; n0 < nbeg + NSEQ / NCHUNK; n0 += 32) {
#pragma unroll 8
        for (int nn = 0; nn < 32; nn++)
            Es[nn * 256 + tid] = Pb[(size_t)(n0 + nn) * RRANK + tid];
#pragma unroll
        for (int i = 0; i < 8; i++) {
            int idx = i * 256 + tid;
            int nn = idx >> 6, dep = idx & 63;
            Ks[nn * 68 + dep] = Sb[(size_t)(n0 + nn) * DMODEL + dep];
        }
        __syncthreads();
        for (int nn = 0; nn < 32; nn += 2) {
            float e0 = Es[nn * 256 + tid];
            float e1 = Es[nn * 256 + 256 + tid];
#pragma unroll
            for (int d = 0; d < 64; d += 4) {
                float4 k0 = *(const float4*)&Ks[nn * 68 + d];
                float4 k1 = *(const float4*)&Ks[nn * 68 + 68 + d];
                acc[d + 0] = fmaf(e1, k1.x, fmaf(e0, k0.x, acc[d + 0]));
                acc[d + 1] = fmaf(e1, k1.y, fmaf(e0, k0.y, acc[d + 1]));
                acc[d + 2] = fmaf(e1, k1.z, fmaf(e0, k0.z, acc[d + 2]));
                acc[d + 3] = fmaf(e1, k1.w, fmaf(e0, k0.w, acc[d + 3]));
            }
        }
        __syncthreads();
    }

    float* o = partial + (size_t)chunk * (64 * 256 * 64) + ((size_t)bh * 256 + tid) * 64;
#pragma unroll
    for (int d = 0; d < 64; d += 4)
        *(float4*)&o[d] = make_float4(acc[d], acc[d + 1], acc[d + 2], acc[d + 3]);
}

__global__ void reduce_partials(const float* __restrict__ part, float* __restrict__ out) {
    int i = blockIdx.x * 256 + threadIdx.x;
    float s = 0.f;
#pragma unroll
    for (int c = 0; c < NCHUNK; c++) s += part[(size_t)c * 1048576 + i];
    out[i] = s;
}

// ---------------- fused attention: scores -> softmax -> @v_proj ----------------
__global__ void attn_kernel(const float* __restrict__ q, const float* __restrict__ kp,
                            const float* __restrict__ vp, float* __restrict__ outc) {
    extern __shared__ float sm[];
    float* Qs  = sm;                 // 4160 floats
    float* KpS = sm + 4160;          // 16896 floats (Kp then reused as S)
    float* Vp  = sm + 21056;         // 17408 floats
    __shared__ float red[64 * 32];

    const int m0 = blockIdx.x * 64;
    const int bh = blockIdx.y;
    const int b = bh >> 3, h = bh & 7;
    const int tid = threadIdx.x;

    const float* qb = q + ((size_t)b * NSEQ + m0) * DMODEL + h * DEPTH;
#pragma unroll
    for (int i = 0; i < 16; i++) {
        int idx = i * 256 + tid;
        int m = idx >> 6, dep = idx & 63;
        Qs[m * 65 + dep] = qb[(size_t)m * DMODEL + dep] * 0.125f;
    }
    const float* kpb = kp + (size_t)bh * RRANK * DEPTH;
    const float* vpb = vp + (size_t)bh * RRANK * DEPTH;
#pragma unroll
    for (int i = 0; i < 64; i++) {
        int idx = i * 256 + tid;
        int r = idx >> 6, dep = idx & 63;
        KpS[r * 65 + dep] = kpb[idx];
        Vp[r * 68 + dep] = vpb[idx];
    }
    __syncthreads();

    const int tx = tid & 31, ty = tid >> 5;
    float acc[8][8];
#pragma unroll
    for (int i = 0; i < 8; i++)
#pragma unroll
        for (int j = 0; j < 8; j++) acc[i][j] = 0.f;

    for (int dep = 0; dep < 64; dep++) {
        float ra[8], rb[8];
#pragma unroll
        for (int i = 0; i < 8; i++) ra[i] = Qs[(ty * 8 + i) * 65 + dep];
#pragma unroll
        for (int j = 0; j < 8; j++) rb[j] = KpS[(tx * 8 + j) * 65 + dep];
#pragma unroll
        for (int i = 0; i < 8; i++)
#pragma unroll
            for (int j = 0; j < 8; j++) acc[i][j] = fmaf(ra[i], rb[j], acc[i][j]);
    }

    float rowmax[8], inv[8];
#pragma unroll
    for (int i = 0; i < 8; i++) {
        float pm = acc[i][0];
#pragma unroll
        for (int j = 1; j < 8; j++) pm = fmaxf(pm, acc[i][j]);
        red[(ty * 8 + i) * 32 + tx] = pm;
    }
    __syncthreads();
#pragma unroll
    for (int i = 0; i < 8; i++) {
        float mx = red[(ty * 8 + i) * 32];
        for (int j2 = 1; j2 < 32; j2++) mx = fmaxf(mx, red[(ty * 8 + i) * 32 + j2]);
        rowmax[i] = mx;
    }
    __syncthreads();
#pragma unroll
    for (int i = 0; i < 8; i++) {
        float s = 0.f;
#pragma unroll
        for (int j = 0; j < 8; j++) {
            acc[i][j] = __expf(acc[i][j] - rowmax[i]);
            s += acc[i][j];
        }
        red[(ty * 8 + i) * 32 + tx] = s;
    }
    __syncthreads();
#pragma unroll
    for (int i = 0; i < 8; i++) {
        float s = red[(ty * 8 + i) * 32];
        for (int j2 = 1; j2 < 32; j2++) s += red[(ty * 8 + i) * 32 + j2];
        inv[i] = 1.0f / s;
    }

#pragma unroll
    for (int i = 0; i < 8; i++) {
#pragma unroll
        for (int j = 0; j < 8; j += 4) {
            float4 pv = make_float4(acc[i][j] * inv[i], acc[i][j + 1] * inv[i],
                                    acc[i][j + 2] * inv[i], acc[i][j + 3] * inv[i]);
            *(float4*)&KpS[(ty * 8 + i) * 264 + tx * 8 + j] = pv;
        }
    }
    __syncthreads();

    const int tx2 = tid & 15, ty2 = tid >> 4;
    float o[4][4];
#pragma unroll
    for (int i = 0; i < 4; i++)
#pragma unroll
        for (int j = 0; j < 4; j++) o[i][j] = 0.f;

    for (int r = 0; r < 256; r++) {
        float4 vv = *(const float4*)&Vp[r * 68 + tx2 * 4];
#pragma unroll
        for (int i = 0; i < 4; i++) {
            float a = KpS[(ty2 * 4 + i) * 264 + r];
            o[i][0] = fmaf(a, vv.x, o[i][0]);
            o[i][1] = fmaf(a, vv.y, o[i][1]);
            o[i][2] = fmaf(a, vv.z, o[i][2]);
            o[i][3] = fmaf(a, vv.w, o[i][3]);
        }
    }

    float* ob = outc + ((size_t)b * NSEQ + m0) * DMODEL + h * DEPTH;
#pragma unroll
    for (int i = 0; i < 4; i++)
        *(float4*)&ob[(size_t)(ty2 * 4 + i) * DMODEL + tx2 * 4] =
            make_float4(o[i][0], o[i][1], o[i][2], o[i][3]);
}

// ---------------- launch ----------------
extern "C" void kernel_launch(void* const* d_in, const int* in_sizes, int n_in,
                              void* d_out, int out_size) {
    const float* x  = (const float*)d_in[0];
    const float* wq = (const float*)d_in[1];
    const float* wk = (const float*)d_in[2];
    const float* wv = (const float*)d_in[3];
    const float* E  = (const float*)d_in[4];
    const float* F  = (const float*)d_in[5];
    const float* wd = (const float*)d_in[6];
    const float* bd = (const float*)d_in[7];
    float* out = (float*)d_out;

    float *gq, *gk, *gv, *gpart, *gkp, *gvp, *gcat;
    __nv_bfloat16 *gxhi, *gxlo, *gchi, *gclo, *gwhi, *gwlo;
    cudaGetSymbolAddress((void**)&gq, g_q);
    cudaGetSymbolAddress((void**)&gk, g_k);
    cudaGetSymbolAddress((void**)&gv, g_v);
    cudaGetSymbolAddress((void**)&gpart, g_part);
    cudaGetSymbolAddress((void**)&gkp, g_kp);
    cudaGetSymbolAddress((void**)&gvp, g_vp);
    cudaGetSymbolAddress((void**)&gcat, g_cat);
    cudaGetSymbolAddress((void**)&gxhi, g_xhi);
    cudaGetSymbolAddress((void**)&gxlo, g_xlo);
    cudaGetSymbolAddress((void**)&gchi, g_chi);
    cudaGetSymbolAddress((void**)&gclo, g_clo);
    cudaGetSymbolAddress((void**)&gwhi, g_whi);
    cudaGetSymbolAddress((void**)&gwlo, g_wlo);

    // split inputs into bf16 hi/lo
    cvt_split<<<MROWS * DMODEL / 256, 256>>>(x, gxhi, gxlo, MROWS * DMODEL);
    cvt_split<<<DMODEL * DMODEL / 256, 256>>>(wq, gwhi + 0 * 262144, gwlo + 0 * 262144, DMODEL * DMODEL);
    cvt_split<<<DMODEL * DMODEL / 256, 256>>>(wk, gwhi + 1 * 262144, gwlo + 1 * 262144, DMODEL * DMODEL);
    cvt_split<<<DMODEL * DMODEL / 256, 256>>>(wv, gwhi + 2 * 262144, gwlo + 2 * 262144, DMODEL * DMODEL);
    cvt_split<<<DMODEL * DMODEL / 256, 256>>>(wd, gwhi + 3 * 262144, gwlo + 3 * 262144, DMODEL * DMODEL);

    dim3 gg(DMODEL / 128, MROWS / 128);   // (4, 256)
    mma_gemm<<<gg, 256>>>(gxhi, gxlo, gwhi + 0 * 262144, gwlo + 0 * 262144, nullptr, gq, MROWS, DMODEL, DMODEL);
    mma_gemm<<<gg, 256>>>(gxhi, gxlo, gwhi + 1 * 262144, gwlo + 1 * 262144, nullptr, gk, MROWS, DMODEL, DMODEL);
    mma_gemm<<<gg, 256>>>(gxhi, gxlo, gwhi + 2 * 262144, gwlo + 2 * 262144, nullptr, gv, MROWS, DMODEL, DMODEL);

    proj_kernel<<<dim3(BATCH * HEADS, NCHUNK), 256>>>(gk, E, gpart);
    reduce_partials<<<1048576 / 256, 256>>>(gpart, gkp);
    proj_kernel<<<dim3(BATCH * HEADS, NCHUNK), 256>>>(gv, F, gpart);
    reduce_partials<<<1048576 / 256, 256>>>(gpart, gvp);

    cudaFuncSetAttribute(attn_kernel, cudaFuncAttributeMaxDynamicSharedMemorySize, 153856);
    attn_kernel<<<dim3(NSEQ / 64, BATCH * HEADS), 256, 153856>>>(gq, gkp, gvp, gcat);

    cvt_split<<<MROWS * DMODEL / 256, 256>>>(gcat, gchi, gclo, MROWS * DMODEL);
    mma_gemm<<<gg, 256>>>(gchi, gclo, gwhi + 3 * 262144, gwlo + 3 * 262144, bd, out, MROWS, DMODEL, DMODEL);
}

// round 8
// speedup vs baseline: 2.9217x; 2.1296x over previous
#include <cuda_runtime.h>
#include <cuda_bf16.h>
#include <cstddef>
#include <cstdint>

typedef __nv_bfloat16 bf16;

#define NSEQ   4096
#define BATCH  8
#define DMODEL 512
#define HEADS  8
#define RRANK  256
#define DEPTH  64
#define MROWS  32768
#define NCHUNK 8

// ---------------- scratch (static device allocations only) ----------------
__device__ float g_part[8388608];            // NCHUNK x 64 x 16384 fp32 partials
__device__ bf16 g_xh[16777216], g_xl[16777216];
__device__ bf16 g_wh[1048576],  g_wl[1048576];       // wq|wk|wv|wd slabs of 262144
__device__ bf16 g_qh[16777216], g_ql[16777216];
__device__ bf16 g_kh[16777216], g_kl[16777216];
__device__ bf16 g_vh[16777216], g_vl[16777216];
__device__ bf16 g_Eh[8388608],  g_El[8388608];
__device__ bf16 g_Fh[8388608],  g_Fl[8388608];
__device__ bf16 g_kpth[1048576], g_kptl[1048576];    // [bh][64][256]  (kp transposed)
__device__ bf16 g_vph[1048576],  g_vpl[1048576];     // [bh][256][64]
__device__ bf16 g_cath[16777216], g_catl[16777216];

// ---------------- fp32 -> bf16 hi/lo split ----------------
__global__ void cvt_split(const float* __restrict__ in, bf16* __restrict__ hi,
                          bf16* __restrict__ lo, int n) {
    int i = blockIdx.x * 256 + threadIdx.x;
    if (i < n) {
        float v = in[i];
        bf16 h = __float2bfloat16(v);
        hi[i] = h;
        lo[i] = __float2bfloat16(v - __bfloat162float(h));
    }
}

// ---------------- mma helpers ----------------
__device__ __forceinline__ void ldsm4(uint32_t r[4], const void* p) {
    uint32_t a = (uint32_t)__cvta_generic_to_shared(p);
    asm volatile("ldmatrix.sync.aligned.m8n8.x4.shared.b16 {%0,%1,%2,%3}, [%4];"
                 : "=r"(r[0]), "=r"(r[1]), "=r"(r[2]), "=r"(r[3]) : "r"(a));
}
__device__ __forceinline__ void ldsm4t(uint32_t r[4], const void* p) {
    uint32_t a = (uint32_t)__cvta_generic_to_shared(p);
    asm volatile("ldmatrix.sync.aligned.m8n8.x4.trans.shared.b16 {%0,%1,%2,%3}, [%4];"
                 : "=r"(r[0]), "=r"(r[1]), "=r"(r[2]), "=r"(r[3]) : "r"(a));
}
__device__ __forceinline__ void mma16816(float c[4], const uint32_t a[4],
                                         uint32_t b0, uint32_t b1) {
    asm volatile("mma.sync.aligned.m16n8k16.row.col.f32.bf16.bf16.f32 "
                 "{%0,%1,%2,%3},{%4,%5,%6,%7},{%8,%9},{%0,%1,%2,%3};"
                 : "+f"(c[0]), "+f"(c[1]), "+f"(c[2]), "+f"(c[3])
                 : "r"(a[0]), "r"(a[1]), "r"(a[2]), "r"(a[3]), "r"(b0), "r"(b1));
}
__device__ __forceinline__ uint32_t packb(bf16 a, bf16 b) {
    __nv_bfloat162 t; t.x = a; t.y = b;
    return *reinterpret_cast<uint32_t*>(&t);
}
// split f32 pair -> (hi-pack, lo-pack)
__device__ __forceinline__ void split2(float v0, float v1, uint32_t& hp, uint32_t& lp) {
    bf16 h0 = __float2bfloat16(v0), h1 = __float2bfloat16(v1);
    hp = packb(h0, h1);
    lp = packb(__float2bfloat16(v0 - __bfloat162float(h0)),
               __float2bfloat16(v1 - __bfloat162float(h1)));
}

// ---------------- tensor-core GEMM: C = (Ahi+Alo)@(Bhi+Blo) approx ----------------
// BM=128, BN=128, BK=32, 256 threads = 8 warps (2x4), warp tile 64x32.
// If Chi != nullptr: write bf16 hi/lo split outputs. Else fp32 (+bias) to C.
__global__ __launch_bounds__(256, 2)
void mma_gemm(const bf16* __restrict__ Ahi_, const bf16* __restrict__ Alo_,
              const bf16* __restrict__ Bhi_, const bf16* __restrict__ Blo_,
              const float* __restrict__ bias, float* __restrict__ C,
              bf16* __restrict__ Chi, bf16* __restrict__ Clo,
              int M, int K, int Nn) {
    __shared__ __align__(16) bf16 sAh[128 * 40];
    __shared__ __align__(16) bf16 sAl[128 * 40];
    __shared__ __align__(16) bf16 sBh[32 * 136];
    __shared__ __align__(16) bf16 sBl[32 * 136];

    const int tid  = threadIdx.x;
    const int lane = tid & 31, warp = tid >> 5;
    const int wm = (warp >> 2) * 64;
    const int wn = (warp & 3) * 32;
    const int bRow = blockIdx.y * 128, bCol = blockIdx.x * 128;

    float acc[4][4][4];
#pragma unroll
    for (int i = 0; i < 4; i++)
#pragma unroll
        for (int j = 0; j < 4; j++)
#pragma unroll
            for (int c = 0; c < 4; c++) acc[i][j][c] = 0.f;

    const int arow = tid >> 2, acol = (tid & 3) * 8;
    const int brow = tid >> 4, bcol = (tid & 15) * 8;

    for (int kt = 0; kt < K; kt += 32) {
#pragma unroll
        for (int rr = 0; rr < 2; rr++) {
            int r = arow + rr * 64;
            size_t go = (size_t)(bRow + r) * K + kt + acol;
            *(uint4*)&sAh[r * 40 + acol] = *(const uint4*)(Ahi_ + go);
            *(uint4*)&sAl[r * 40 + acol] = *(const uint4*)(Alo_ + go);
        }
#pragma unroll
        for (int rr = 0; rr < 2; rr++) {
            int r = brow + rr * 16;
            size_t go = (size_t)(kt + r) * Nn + bCol + bcol;
            *(uint4*)&sBh[r * 136 + bcol] = *(const uint4*)(Bhi_ + go);
            *(uint4*)&sBl[r * 136 + bcol] = *(const uint4*)(Blo_ + go);
        }
        __syncthreads();
#pragma unroll
        for (int ks = 0; ks < 2; ks++) {
            uint32_t ah[4][4], al[4][4];
            const int ar = wm + (lane & 15);
            const int ac = ks * 16 + (lane >> 4) * 8;
#pragma unroll
            for (int mi = 0; mi < 4; mi++) {
                ldsm4(ah[mi], &sAh[(ar + mi * 16) * 40 + ac]);
                ldsm4(al[mi], &sAl[(ar + mi * 16) * 40 + ac]);
            }
            const int br = ks * 16 + (lane & 15);
#pragma unroll
            for (int jp = 0; jp < 2; jp++) {
                uint32_t bh[4], bl[4];
                const int bc = wn + jp * 16 + (lane >> 4) * 8;
                ldsm4t(bh, &sBh[br * 136 + bc]);
                ldsm4t(bl, &sBl[br * 136 + bc]);
#pragma unroll
                for (int h = 0; h < 2; h++) {
#pragma unroll
                    for (int mi = 0; mi < 4; mi++) {
                        float* a4 = acc[mi][jp * 2 + h];
                        mma16816(a4, ah[mi], bh[h * 2], bh[h * 2 + 1]);
                        mma16816(a4, ah[mi], bl[h * 2], bl[h * 2 + 1]);
                        mma16816(a4, al[mi], bh[h * 2], bh[h * 2 + 1]);
                    }
                }
            }
        }
        __syncthreads();
    }

    const int gid = lane >> 2, qid = lane & 3;
#pragma unroll
    for (int mi = 0; mi < 4; mi++) {
        const int row = bRow + wm + mi * 16 + gid;
#pragma unroll
        for (int nj = 0; nj < 4; nj++) {
            const int col = bCol + wn + nj * 8 + qid * 2;
            if (Chi) {
                uint32_t hp, lp;
                split2(acc[mi][nj][0], acc[mi][nj][1], hp, lp);
                *(uint32_t*)&Chi[(size_t)row * Nn + col] = hp;
                *(uint32_t*)&Clo[(size_t)row * Nn + col] = lp;
                split2(acc[mi][nj][2], acc[mi][nj][3], hp, lp);
                *(uint32_t*)&Chi[(size_t)(row + 8) * Nn + col] = hp;
                *(uint32_t*)&Clo[(size_t)(row + 8) * Nn + col] = lp;
            } else {
                float b0 = 0.f, b1 = 0.f;
                if (bias) { b0 = bias[col]; b1 = bias[col + 1]; }
                *(float2*)&C[(size_t)row * Nn + col] =
                    make_float2(acc[mi][nj][0] + b0, acc[mi][nj][1] + b1);
                *(float2*)&C[(size_t)(row + 8) * Nn + col] =
                    make_float2(acc[mi][nj][2] + b0, acc[mi][nj][3] + b1);
            }
        }
    }
}

// ---------------- proj K-path: C[d=64][r=256] = K^T @ E, per (bh, chunk) ----------------
// grid (64, NCHUNK), 256 threads = 8 warps; warp tile 16(m=d) x 128(n=r).
__global__ __launch_bounds__(256, 2)
void projK(const bf16* __restrict__ Kh_, const bf16* __restrict__ Kl_,
           const bf16* __restrict__ Eh_, const bf16* __restrict__ El_,
           float* __restrict__ part) {
    __shared__ __align__(16) bf16 sEh[32 * 264], sEl[32 * 264];
    __shared__ __align__(16) bf16 sKh[32 * 72],  sKl[32 * 72];
    const int tid = threadIdx.x, lane = tid & 31, warp = tid >> 5;
    const int bh = blockIdx.x, b = bh >> 3, h = bh & 7, chunk = blockIdx.y;
    const int wm = (warp & 3) * 16;      // d
    const int wn = (warp >> 2) * 128;    // r

    float c[16][4];
#pragma unroll
    for (int t = 0; t < 16; t++)
#pragma unroll
        for (int j = 0; j < 4; j++) c[t][j] = 0.f;

    for (int it = 0; it < 16; it++) {
        const int nb = chunk * 512 + it * 32;
#pragma unroll
        for (int i = 0; i < 4; i++) {
            int u = tid + 256 * i, r = u >> 5, c8 = (u & 31) * 8;
            size_t go = ((size_t)h * NSEQ + nb + r) * RRANK + c8;
            *(uint4*)&sEh[r * 264 + c8] = *(const uint4*)(Eh_ + go);
            *(uint4*)&sEl[r * 264 + c8] = *(const uint4*)(El_ + go);
        }
        {
            int r = tid >> 3, c8 = (tid & 7) * 8;
            size_t go = ((size_t)b * NSEQ + nb + r) * DMODEL + h * DEPTH + c8;
            *(uint4*)&sKh[r * 72 + c8] = *(const uint4*)(Kh_ + go);
            *(uint4*)&sKl[r * 72 + c8] = *(const uint4*)(Kl_ + go);
        }
        __syncthreads();
#pragma unroll
        for (int ks = 0; ks < 2; ks++) {
            uint32_t ah[4], al[4];
            const int krow = ks * 16 + (lane & 7) + ((lane >> 4) << 3);
            const int mcol = wm + (((lane >> 3) & 1) << 3);
            ldsm4t(ah, &sKh[krow * 72 + mcol]);       // trans-A: K^T fragments
            ldsm4t(al, &sKl[krow * 72 + mcol]);
            const int brow = ks * 16 + (lane & 15);
#pragma unroll
            for (int t = 0; t < 8; t++) {
                uint32_t beh[4], bel[4];
                const int bc = wn + t * 16 + (lane >> 4) * 8;
                ldsm4t(beh, &sEh[brow * 264 + bc]);
                ldsm4t(bel, &sEl[brow * 264 + bc]);
#pragma unroll
                for (int h2 = 0; h2 < 2; h2++) {
                    float* cc = c[t * 2 + h2];
                    mma16816(cc, ah, beh[h2 * 2], beh[h2 * 2 + 1]);
                    mma16816(cc, ah, bel[h2 * 2], bel[h2 * 2 + 1]);
                    mma16816(cc, al, beh[h2 * 2], beh[h2 * 2 + 1]);
                }
            }
        }
        __syncthreads();
    }
    const int g = lane >> 2, q = lane & 3;
    float* pb = part + ((size_t)(chunk * 64 + bh)) * 16384;
#pragma unroll
    for (int t = 0; t < 16; t++) {
        const int col = wn + t * 8 + q * 2;
        const int row = wm + g;
        *(float2*)&pb[row * 256 + col]       = make_float2(c[t][0], c[t][1]);
        *(float2*)&pb[(row + 8) * 256 + col] = make_float2(c[t][2], c[t][3]);
    }
}

// ---------------- proj V-path: C[r=256][d=64] = F^T @ V, per (bh, chunk) ----------------
// warp tile 64(m=r) x 32(n=d); warps (4,2).
__global__ __launch_bounds__(256, 2)
void projV(const bf16* __restrict__ Fh_, const bf16* __restrict__ Fl_,
           const bf16* __restrict__ Vh_, const bf16* __restrict__ Vl_,
           float* __restrict__ part) {
    __shared__ __align__(16) bf16 sFh[32 * 264], sFl[32 * 264];
    __shared__ __align__(16) bf16 sVh[32 * 72],  sVl[32 * 72];
    const int tid = threadIdx.x, lane = tid & 31, warp = tid >> 5;
    const int bh = blockIdx.x, b = bh >> 3, h = bh & 7, chunk = blockIdx.y;
    const int wm = (warp >> 1) * 64;     // r
    const int wn = (warp & 1) * 32;      // d

    float c[4][4][4];
#pragma unroll
    for (int i = 0; i < 4; i++)
#pragma unroll
        for (int j = 0; j < 4; j++)
#pragma unroll
            for (int k = 0; k < 4; k++) c[i][j][k] = 0.f;

    for (int it = 0; it < 16; it++) {
        const int nb = chunk * 512 + it * 32;
#pragma unroll
        for (int i = 0; i < 4; i++) {
            int u = tid + 256 * i, r = u >> 5, c8 = (u & 31) * 8;
            size_t go = ((size_t)h * NSEQ + nb + r) * RRANK + c8;
            *(uint4*)&sFh[r * 264 + c8] = *(const uint4*)(Fh_ + go);
            *(uint4*)&sFl[r * 264 + c8] = *(const uint4*)(Fl_ + go);
        }
        {
            int r = tid >> 3, c8 = (tid & 7) * 8;
            size_t go = ((size_t)b * NSEQ + nb + r) * DMODEL + h * DEPTH + c8;
            *(uint4*)&sVh[r * 72 + c8] = *(const uint4*)(Vh_ + go);
            *(uint4*)&sVl[r * 72 + c8] = *(const uint4*)(Vl_ + go);
        }
        __syncthreads();
#pragma unroll
        for (int ks = 0; ks < 2; ks++) {
            uint32_t ah[4][4], al[4][4];
#pragma unroll
            for (int mi = 0; mi < 4; mi++) {
                const int krow = ks * 16 + (lane & 7) + ((lane >> 4) << 3);
                const int mcol = wm + mi * 16 + (((lane >> 3) & 1) << 3);
                ldsm4t(ah[mi], &sFh[krow * 264 + mcol]);  // trans-A: F^T
                ldsm4t(al[mi], &sFl[krow * 264 + mcol]);
            }
            const int brow = ks * 16 + (lane & 15);
#pragma unroll
            for (int t = 0; t < 2; t++) {
                uint32_t bvh[4], bvl[4];
                const int bc = wn + t * 16 + (lane >> 4) * 8;
                ldsm4t(bvh, &sVh[brow * 72 + bc]);
                ldsm4t(bvl, &sVl[brow * 72 + bc]);
#pragma unroll
                for (int h2 = 0; h2 < 2; h2++) {
#pragma unroll
                    for (int mi = 0; mi < 4; mi++) {
                        float* cc = c[mi][t * 2 + h2];
                        mma16816(cc, ah[mi], bvh[h2 * 2], bvh[h2 * 2 + 1]);
                        mma16816(cc, ah[mi], bvl[h2 * 2], bvl[h2 * 2 + 1]);
                        mma16816(cc, al[mi], bvh[h2 * 2], bvh[h2 * 2 + 1]);
                    }
                }
            }
        }
        __syncthreads();
    }
    const int g = lane >> 2, q = lane & 3;
    float* pb = part + ((size_t)(chunk * 64 + bh)) * 16384;
#pragma unroll
    for (int mi = 0; mi < 4; mi++) {
        const int row = wm + mi * 16 + g;
#pragma unroll
        for (int nj = 0; nj < 4; nj++) {
            const int col = wn + nj * 8 + q * 2;
            *(float2*)&pb[row * 64 + col]       = make_float2(c[mi][nj][0], c[mi][nj][1]);
            *(float2*)&pb[(row + 8) * 64 + col] = make_float2(c[mi][nj][2], c[mi][nj][3]);
        }
    }
}

// ---------------- reduce partials -> bf16 hi/lo ----------------
__global__ void reduce_split(const float* __restrict__ part, bf16* __restrict__ oh,
                             bf16* __restrict__ ol) {
    int i = blockIdx.x * 256 + threadIdx.x;
    float s = 0.f;
#pragma unroll
    for (int c = 0; c < NCHUNK; c++) s += part[(size_t)c * 1048576 + i];
    bf16 h = __float2bfloat16(s);
    oh[i] = h;
    ol[i] = __float2bfloat16(s - __bfloat162float(h));
}

// ---------------- fused tensor-core attention ----------------
// grid (NSEQ/128, 64). 8 warps, warp owns 16 rows x full r=256.
__global__ __launch_bounds__(256, 1)
void attn_mma(const bf16* __restrict__ qh_, const bf16* __restrict__ ql_,
              const bf16* __restrict__ kph_, const bf16* __restrict__ kpl_,
              const bf16* __restrict__ vph_, const bf16* __restrict__ vpl_,
              bf16* __restrict__ cath, bf16* __restrict__ catl) {
    extern __shared__ bf16 dsm[];
    bf16* sQh = dsm;             // 128 x 72
    bf16* sQl = sQh + 9216;
    bf16* sKh = sQl + 9216;      // 64 x 264 (kp^T)
    bf16* sKl = sKh + 16896;
    bf16* sVh = sKl + 16896;     // 256 x 72
    bf16* sVl = sVh + 18432;

    const int tid = threadIdx.x, lane = tid & 31, warp = tid >> 5;
    const int m0 = blockIdx.x * 128;
    const int bh = blockIdx.y, b = bh >> 3, h = bh & 7;

    // loads
#pragma unroll
    for (int i = 0; i < 4; i++) {
        int u = tid + 256 * i, r = u >> 3, c8 = (u & 7) * 8;
        size_t go = ((size_t)(b * NSEQ + m0 + r)) * DMODEL + h * DEPTH + c8;
        *(uint4*)&sQh[r * 72 + c8] = *(const uint4*)(qh_ + go);
        *(uint4*)&sQl[r * 72 + c8] = *(const uint4*)(ql_ + go);
    }
#pragma unroll
    for (int i = 0; i < 8; i++) {
        int u = tid + 256 * i, r = u >> 5, c8 = (u & 31) * 8;
        size_t go = (size_t)bh * 16384 + (size_t)r * 256 + c8;
        *(uint4*)&sKh[r * 264 + c8] = *(const uint4*)(kph_ + go);
        *(uint4*)&sKl[r * 264 + c8] = *(const uint4*)(kpl_ + go);
    }
#pragma unroll
    for (int i = 0; i < 8; i++) {
        int u = tid + 256 * i, r = u >> 3, c8 = (u & 7) * 8;
        size_t go = (size_t)bh * 16384 + (size_t)r * 64 + c8;
        *(uint4*)&sVh[r * 72 + c8] = *(const uint4*)(vph_ + go);
        *(uint4*)&sVl[r * 72 + c8] = *(const uint4*)(vpl_ + go);
    }
    __syncthreads();

    const int wm = warp * 16;
    float c[32][4];
#pragma unroll
    for (int t = 0; t < 32; t++)
#pragma unroll
        for (int j = 0; j < 4; j++) c[t][j] = 0.f;

    // scores: S[16 x 256] = Q @ kp^T (3-term split)
#pragma unroll
    for (int kd = 0; kd < 4; kd++) {
        uint32_t ah4[4], al4[4];
        const int ar = wm + (lane & 15);
        const int ac = kd * 16 + (lane >> 4) * 8;
        ldsm4(ah4, &sQh[ar * 72 + ac]);
        ldsm4(al4, &sQl[ar * 72 + ac]);
        const int brow = kd * 16 + (lane & 15);
#pragma unroll
        for (int t = 0; t < 16; t++) {
            uint32_t bh4[4], bl4[4];
            const int bc = t * 16 + (lane >> 4) * 8;
            ldsm4t(bh4, &sKh[brow * 264 + bc]);
            ldsm4t(bl4, &sKl[brow * 264 + bc]);
#pragma unroll
            for (int h2 = 0; h2 < 2; h2++) {
                float* cc = c[t * 2 + h2];
                mma16816(cc, ah4, bh4[h2 * 2], bh4[h2 * 2 + 1]);
                mma16816(cc, ah4, bl4[h2 * 2], bl4[h2 * 2 + 1]);
                mma16816(cc, al4, bh4[h2 * 2], bh4[h2 * 2 + 1]);
            }
        }
    }

    // softmax (rows g and g+8 of this quad, full r in-warp)
#pragma unroll
    for (int t = 0; t < 32; t++)
#pragma unroll
        for (int j = 0; j < 4; j++) c[t][j] *= 0.125f;

    float mx0 = -1e30f, mx1 = -1e30f;
#pragma unroll
    for (int t = 0; t < 32; t++) {
        mx0 = fmaxf(mx0, fmaxf(c[t][0], c[t][1]));
        mx1 = fmaxf(mx1, fmaxf(c[t][2], c[t][3]));
    }
    mx0 = fmaxf(mx0, __shfl_xor_sync(0xffffffffu, mx0, 1));
    mx0 = fmaxf(mx0, __shfl_xor_sync(0xffffffffu, mx0, 2));
    mx1 = fmaxf(mx1, __shfl_xor_sync(0xffffffffu, mx1, 1));
    mx1 = fmaxf(mx1, __shfl_xor_sync(0xffffffffu, mx1, 2));

    float s0 = 0.f, s1 = 0.f;
#pragma unroll
    for (int t = 0; t < 32; t++) {
        c[t][0] = __expf(c[t][0] - mx0); s0 += c[t][0];
        c[t][1] = __expf(c[t][1] - mx0); s0 += c[t][1];
        c[t][2] = __expf(c[t][2] - mx1); s1 += c[t][2];
        c[t][3] = __expf(c[t][3] - mx1); s1 += c[t][3];
    }
    s0 += __shfl_xor_sync(0xffffffffu, s0, 1);
    s0 += __shfl_xor_sync(0xffffffffu, s0, 2);
    s1 += __shfl_xor_sync(0xffffffffu, s1, 1);
    s1 += __shfl_xor_sync(0xffffffffu, s1, 2);
    const float inv0 = 1.0f / s0, inv1 = 1.0f / s1;

    // pack P fragments (C-frag layout == A-frag layout for the PV mma)
    uint32_t phi[32][2], plo[32][2];
#pragma unroll
    for (int t = 0; t < 32; t++) {
        split2(c[t][0] * inv0, c[t][1] * inv0, phi[t][0], plo[t][0]);
        split2(c[t][2] * inv1, c[t][3] * inv1, phi[t][1], plo[t][1]);
    }

    // O[16 x 64] = P @ Vp (3-term split)
    float o[8][4];
#pragma unroll
    for (int j = 0; j < 8; j++)
#pragma unroll
        for (int k = 0; k < 4; k++) o[j][k] = 0.f;

#pragma unroll
    for (int rk = 0; rk < 16; rk++) {
        uint32_t pah[4] = { phi[2 * rk][0], phi[2 * rk][1], phi[2 * rk + 1][0], phi[2 * rk + 1][1] };
        uint32_t pal[4] = { plo[2 * rk][0], plo[2 * rk][1], plo[2 * rk + 1][0], plo[2 * rk + 1][1] };
        const int brow = rk * 16 + (lane & 15);
#pragma unroll
        for (int db = 0; db < 4; db++) {
            uint32_t vh4[4], vl4[4];
            const int bc = db * 16 + (lane >> 4) * 8;
            ldsm4t(vh4, &sVh[brow * 72 + bc]);
            ldsm4t(vl4, &sVl[brow * 72 + bc]);
#pragma unroll
            for (int h2 = 0; h2 < 2; h2++) {
                float* oo = o[db * 2 + h2];
                mma16816(oo, pah, vh4[h2 * 2], vh4[h2 * 2 + 1]);
                mma16816(oo, pal, vh4[h2 * 2], vh4[h2 * 2 + 1]);
                mma16816(oo, pah, vl4[h2 * 2], vl4[h2 * 2 + 1]);
            }
        }
    }

    // epilogue: write cat hi/lo
    const int g = lane >> 2, q = lane & 3;
    const size_t row0 = (size_t)(b * NSEQ + m0 + wm + g);
#pragma unroll
    for (int j = 0; j < 8; j++) {
        const int col = h * DEPTH + j * 8 + q * 2;
        uint32_t hp, lp;
        split2(o[j][0], o[j][1], hp, lp);
        *(uint32_t*)&cath[row0 * DMODEL + col] = hp;
        *(uint32_t*)&catl[row0 * DMODEL + col] = lp;
        split2(o[j][2], o[j][3], hp, lp);
        *(uint32_t*)&cath[(row0 + 8) * DMODEL + col] = hp;
        *(uint32_t*)&catl[(row0 + 8) * DMODEL + col] = lp;
    }
}

// ---------------- launch ----------------
extern "C" void kernel_launch(void* const* d_in, const int* in_sizes, int n_in,
                              void* d_out, int out_size) {
    const float* x  = (const float*)d_in[0];
    const float* wq = (const float*)d_in[1];
    const float* wk = (const float*)d_in[2];
    const float* wv = (const float*)d_in[3];
    const float* E  = (const float*)d_in[4];
    const float* F  = (const float*)d_in[5];
    const float* wd = (const float*)d_in[6];
    const float* bd = (const float*)d_in[7];
    float* out = (float*)d_out;

    float* gpart;
    bf16 *gxh, *gxl, *gwh, *gwl, *gqh, *gql, *gkh, *gkl, *gvh, *gvl;
    bf16 *gEh, *gEl, *gFh, *gFl, *gkpth, *gkptl, *gvph, *gvpl, *gcath, *gcatl;
    cudaGetSymbolAddress((void**)&gpart, g_part);
    cudaGetSymbolAddress((void**)&gxh, g_xh);   cudaGetSymbolAddress((void**)&gxl, g_xl);
    cudaGetSymbolAddress((void**)&gwh, g_wh);   cudaGetSymbolAddress((void**)&gwl, g_wl);
    cudaGetSymbolAddress((void**)&gqh, g_qh);   cudaGetSymbolAddress((void**)&gql, g_ql);
    cudaGetSymbolAddress((void**)&gkh, g_kh);   cudaGetSymbolAddress((void**)&gkl, g_kl);
    cudaGetSymbolAddress((void**)&gvh, g_vh);   cudaGetSymbolAddress((void**)&gvl, g_vl);
    cudaGetSymbolAddress((void**)&gEh, g_Eh);   cudaGetSymbolAddress((void**)&gEl, g_El);
    cudaGetSymbolAddress((void**)&gFh, g_Fh);   cudaGetSymbolAddress((void**)&gFl, g_Fl);
    cudaGetSymbolAddress((void**)&gkpth, g_kpth); cudaGetSymbolAddress((void**)&gkptl, g_kptl);
    cudaGetSymbolAddress((void**)&gvph, g_vph); cudaGetSymbolAddress((void**)&gvpl, g_vpl);
    cudaGetSymbolAddress((void**)&gcath, g_cath); cudaGetSymbolAddress((void**)&gcatl, g_catl);

    // splits of raw inputs
    cvt_split<<<MROWS * DMODEL / 256, 256>>>(x, gxh, gxl, MROWS * DMODEL);
    cvt_split<<<1024, 256>>>(wq, gwh + 0 * 262144, gwl + 0 * 262144, 262144);
    cvt_split<<<1024, 256>>>(wk, gwh + 1 * 262144, gwl + 1 * 262144, 262144);
    cvt_split<<<1024, 256>>>(wv, gwh + 2 * 262144, gwl + 2 * 262144, 262144);
    cvt_split<<<1024, 256>>>(wd, gwh + 3 * 262144, gwl + 3 * 262144, 262144);
    cvt_split<<<HEADS * NSEQ * RRANK / 256, 256>>>(E, gEh, gEl, HEADS * NSEQ * RRANK);
    cvt_split<<<HEADS * NSEQ * RRANK / 256, 256>>>(F, gFh, gFl, HEADS * NSEQ * RRANK);

    dim3 gg(DMODEL / 128, MROWS / 128);
    mma_gemm<<<gg, 256>>>(gxh, gxl, gwh + 0 * 262144, gwl + 0 * 262144, nullptr,
                          nullptr, gqh, gql, MROWS, DMODEL, DMODEL);
    mma_gemm<<<gg, 256>>>(gxh, gxl, gwh + 1 * 262144, gwl + 1 * 262144, nullptr,
                          nullptr, gkh, gkl, MROWS, DMODEL, DMODEL);
    mma_gemm<<<gg, 256>>>(gxh, gxl, gwh + 2 * 262144, gwl + 2 * 262144, nullptr,
                          nullptr, gvh, gvl, MROWS, DMODEL, DMODEL);

    projK<<<dim3(BATCH * HEADS, NCHUNK), 256>>>(gkh, gkl, gEh, gEl, gpart);
    reduce_split<<<1048576 / 256, 256>>>(gpart, gkpth, gkptl);
    projV<<<dim3(BATCH * HEADS, NCHUNK), 256>>>(gFh, gFl, gvh, gvl, gpart);
    reduce_split<<<1048576 / 256, 256>>>(gpart, gvph, gvpl);

    cudaFuncSetAttribute(attn_mma, cudaFuncAttributeMaxDynamicSharedMemorySize, 178176);
    attn_mma<<<dim3(NSEQ / 128, BATCH * HEADS), 256, 178176>>>(
        gqh, gql, gkpth, gkptl, gvph, gvpl, gcath, gcatl);

    mma_gemm<<<gg, 256>>>(gcath, gcatl, gwh + 3 * 262144, gwl + 3 * 262144, bd,
                          out, nullptr, nullptr, MROWS, DMODEL, DMODEL);
}

// round 12
// speedup vs baseline: 2.9316x; 1.0034x over previous
#include <cuda_runtime.h>
#include <cuda_bf16.h>
#include <cstddef>
#include <cstdint>

typedef __nv_bfloat16 bf16;

#define NSEQ   4096
#define BATCH  8
#define DMODEL 512
#define HEADS  8
#define RRANK  256
#define DEPTH  64
#define MROWS  32768
#define NCHUNK 8

// ---------------- scratch (static device allocations only) ----------------
__device__ float g_part[8388608];
__device__ bf16 g_xh[16777216], g_xl[16777216];
__device__ bf16 g_wh[1048576],  g_wl[1048576];
__device__ bf16 g_qh[16777216], g_ql[16777216];
__device__ bf16 g_kh[16777216], g_kl[16777216];
__device__ bf16 g_vh[16777216], g_vl[16777216];
__device__ bf16 g_Eh[8388608],  g_El[8388608];
__device__ bf16 g_Fh[8388608],  g_Fl[8388608];
__device__ bf16 g_kpth[1048576], g_kptl[1048576];
__device__ bf16 g_vph[1048576],  g_vpl[1048576];
__device__ bf16 g_cath[16777216], g_catl[16777216];

// ---------------- fp32 -> bf16 hi/lo split ----------------
__global__ void cvt_split(const float* __restrict__ in, bf16* __restrict__ hi,
                          bf16* __restrict__ lo, int n) {
    int i = blockIdx.x * 256 + threadIdx.x;
    if (i < n) {
        float v = in[i];
        bf16 h = __float2bfloat16(v);
        hi[i] = h;
        lo[i] = __float2bfloat16(v - __bfloat162float(h));
    }
}

// ---------------- mma helpers ----------------
__device__ __forceinline__ void ldsm4(uint32_t r[4], const void* p) {
    uint32_t a = (uint32_t)__cvta_generic_to_shared(p);
    asm volatile("ldmatrix.sync.aligned.m8n8.x4.shared.b16 {%0,%1,%2,%3}, [%4];"
                 : "=r"(r[0]), "=r"(r[1]), "=r"(r[2]), "=r"(r[3]) : "r"(a));
}
__device__ __forceinline__ void ldsm4t(uint32_t r[4], const void* p) {
    uint32_t a = (uint32_t)__cvta_generic_to_shared(p);
    asm volatile("ldmatrix.sync.aligned.m8n8.x4.trans.shared.b16 {%0,%1,%2,%3}, [%4];"
                 : "=r"(r[0]), "=r"(r[1]), "=r"(r[2]), "=r"(r[3]) : "r"(a));
}
__device__ __forceinline__ void mma16816(float c[4], const uint32_t a[4],
                                         uint32_t b0, uint32_t b1) {
    asm volatile("mma.sync.aligned.m16n8k16.row.col.f32.bf16.bf16.f32 "
                 "{%0,%1,%2,%3},{%4,%5,%6,%7},{%8,%9},{%0,%1,%2,%3};"
                 : "+f"(c[0]), "+f"(c[1]), "+f"(c[2]), "+f"(c[3])
                 : "r"(a[0]), "r"(a[1]), "r"(a[2]), "r"(a[3]), "r"(b0), "r"(b1));
}
__device__ __forceinline__ uint32_t packb(bf16 a, bf16 b) {
    __nv_bfloat162 t; t.x = a; t.y = b;
    return *reinterpret_cast<uint32_t*>(&t);
}
__device__ __forceinline__ void split2(float v0, float v1, uint32_t& hp, uint32_t& lp) {
    bf16 h0 = __float2bfloat16(v0), h1 = __float2bfloat16(v1);
    hp = packb(h0, h1);
    lp = packb(__float2bfloat16(v0 - __bfloat162float(h0)),
               __float2bfloat16(v1 - __bfloat162float(h1)));
}
__device__ __forceinline__ void cpa16(void* smem_dst, const void* gsrc) {
    uint32_t d = (uint32_t)__cvta_generic_to_shared(smem_dst);
    asm volatile("cp.async.cg.shared.global [%0], [%1], 16;" :: "r"(d), "l"(gsrc));
}
__device__ __forceinline__ void cpa_commit() {
    asm volatile("cp.async.commit_group;");
}
template<int N>
__device__ __forceinline__ void cpa_wait() {
    asm volatile("cp.async.wait_group %0;" :: "n"(N));
}

// ---------------- cp.async double-buffered tensor-core GEMM ----------------
// C = (Ahi+Alo)@(Bhi+Blo) approx (3 terms). BM=128, BN=128, BK=32, 256 thr, 8 warps.
// Dynamic smem layout (halves): sAh[2][5120] | sAl[2][5120] | sBh[2][4352] | sBl[2][4352]
#define SM_AH 0
#define SM_AL 10240
#define SM_BH 20480
#define SM_BL 29184
__global__ __launch_bounds__(256, 2)
void mma_gemm(const bf16* __restrict__ Ahi_, const bf16* __restrict__ Alo_,
              const bf16* __restrict__ Bhi_, const bf16* __restrict__ Blo_,
              const float* __restrict__ bias, float* __restrict__ C,
              bf16* __restrict__ Chi, bf16* __restrict__ Clo,
              int M, int K, int Nn) {
    extern __shared__ bf16 smp[];

    const int tid  = threadIdx.x;
    const int lane = tid & 31, warp = tid >> 5;
    const int wm = (warp >> 2) * 64;
    const int wn = (warp & 3) * 32;
    const int bRow = blockIdx.y * 128, bCol = blockIdx.x * 128;

    float acc[4][4][4];
#pragma unroll
    for (int i = 0; i < 4; i++)
#pragma unroll
        for (int j = 0; j < 4; j++)
#pragma unroll
            for (int c = 0; c < 4; c++) acc[i][j][c] = 0.f;

    const int arow = tid >> 2, acol = (tid & 3) * 8;
    const int brow = tid >> 4, bcol = (tid & 15) * 8;
    const int nIter = K / 32;

    auto prefetch = [&](int st, int kt) {
        bf16* sAh = smp + SM_AH + st * 5120;
        bf16* sAl = smp + SM_AL + st * 5120;
        bf16* sBh = smp + SM_BH + st * 4352;
        bf16* sBl = smp + SM_BL + st * 4352;
#pragma unroll
        for (int rr = 0; rr < 2; rr++) {
            int r = arow + rr * 64;
            size_t go = (size_t)(bRow + r) * K + kt + acol;
            cpa16(&sAh[r * 40 + acol], Ahi_ + go);
            cpa16(&sAl[r * 40 + acol], Alo_ + go);
        }
#pragma unroll
        for (int rr = 0; rr < 2; rr++) {
            int r = brow + rr * 16;
            size_t go = (size_t)(kt + r) * Nn + bCol + bcol;
            cpa16(&sBh[r * 136 + bcol], Bhi_ + go);
            cpa16(&sBl[r * 136 + bcol], Blo_ + go);
        }
        cpa_commit();
    };

    prefetch(0, 0);
    if (nIter > 1) prefetch(1, 32);

    for (int it = 0; it < nIter; it++) {
        const int st = it & 1;
        if (it + 1 < nIter) cpa_wait<1>(); else cpa_wait<0>();
        __syncthreads();

        bf16* sAh = smp + SM_AH + st * 5120;
        bf16* sAl = smp + SM_AL + st * 5120;
        bf16* sBh = smp + SM_BH + st * 4352;
        bf16* sBl = smp + SM_BL + st * 4352;

#pragma unroll
        for (int ks = 0; ks < 2; ks++) {
            uint32_t ah[4][4], al[4][4];
            const int ar = wm + (lane & 15);
            const int ac = ks * 16 + (lane >> 4) * 8;
#pragma unroll
            for (int mi = 0; mi < 4; mi++) {
                ldsm4(ah[mi], &sAh[(ar + mi * 16) * 40 + ac]);
                ldsm4(al[mi], &sAl[(ar + mi * 16) * 40 + ac]);
            }
            const int br = ks * 16 + (lane & 15);
#pragma unroll
            for (int jp = 0; jp < 2; jp++) {
                uint32_t bh[4], bl[4];
                const int bc = wn + jp * 16 + (lane >> 4) * 8;
                ldsm4t(bh, &sBh[br * 136 + bc]);
                ldsm4t(bl, &sBl[br * 136 + bc]);
#pragma unroll
                for (int h = 0; h < 2; h++) {
#pragma unroll
                    for (int mi = 0; mi < 4; mi++) {
                        float* a4 = acc[mi][jp * 2 + h];
                        mma16816(a4, ah[mi], bh[h * 2], bh[h * 2 + 1]);
                        mma16816(a4, ah[mi], bl[h * 2], bl[h * 2 + 1]);
                        mma16816(a4, al[mi], bh[h * 2], bh[h * 2 + 1]);
                    }
                }
            }
        }
        __syncthreads();              // all warps done reading stage st
        if (it + 2 < nIter) prefetch(st, (it + 2) * 32);
    }

    const int gid = lane >> 2, qid = lane & 3;
#pragma unroll
    for (int mi = 0; mi < 4; mi++) {
        const int row = bRow + wm + mi * 16 + gid;
#pragma unroll
        for (int nj = 0; nj < 4; nj++) {
            const int col = bCol + wn + nj * 8 + qid * 2;
            if (Chi) {
                uint32_t hp, lp;
                split2(acc[mi][nj][0], acc[mi][nj][1], hp, lp);
                *(uint32_t*)&Chi[(size_t)row * Nn + col] = hp;
                *(uint32_t*)&Clo[(size_t)row * Nn + col] = lp;
                split2(acc[mi][nj][2], acc[mi][nj][3], hp, lp);
                *(uint32_t*)&Chi[(size_t)(row + 8) * Nn + col] = hp;
                *(uint32_t*)&Clo[(size_t)(row + 8) * Nn + col] = lp;
            } else {
                float b0 = 0.f, b1 = 0.f;
                if (bias) { b0 = bias[col]; b1 = bias[col + 1]; }
                *(float2*)&C[(size_t)row * Nn + col] =
                    make_float2(acc[mi][nj][0] + b0, acc[mi][nj][1] + b1);
                *(float2*)&C[(size_t)(row + 8) * Nn + col] =
                    make_float2(acc[mi][nj][2] + b0, acc[mi][nj][3] + b1);
            }
        }
    }
}
#define GEMM_SMEM (37888 * 2)

// ---------------- proj K-path: C[d=64][r=256] = K^T @ E, per (bh, chunk) ----------------
__global__ __launch_bounds__(256, 2)
void projK(const bf16* __restrict__ Kh_, const bf16* __restrict__ Kl_,
           const bf16* __restrict__ Eh_, const bf16* __restrict__ El_,
           float* __restrict__ part) {
    __shared__ __align__(16) bf16 sEh[32 * 264], sEl[32 * 264];
    __shared__ __align__(16) bf16 sKh[32 * 72],  sKl[32 * 72];
    const int tid = threadIdx.x, lane = tid & 31, warp = tid >> 5;
    const int bh = blockIdx.x, b = bh >> 3, h = bh & 7, chunk = blockIdx.y;
    const int wm = (warp & 3) * 16;
    const int wn = (warp >> 2) * 128;

    float c[16][4];
#pragma unroll
    for (int t = 0; t < 16; t++)
#pragma unroll
        for (int j = 0; j < 4; j++) c[t][j] = 0.f;

    for (int it = 0; it < 16; it++) {
        const int nb = chunk * 512 + it * 32;
#pragma unroll
        for (int i = 0; i < 4; i++) {
            int u = tid + 256 * i, r = u >> 5, c8 = (u & 31) * 8;
            size_t go = ((size_t)h * NSEQ + nb + r) * RRANK + c8;
            *(uint4*)&sEh[r * 264 + c8] = *(const uint4*)(Eh_ + go);
            *(uint4*)&sEl[r * 264 + c8] = *(const uint4*)(El_ + go);
        }
        {
            int r = tid >> 3, c8 = (tid & 7) * 8;
            size_t go = ((size_t)b * NSEQ + nb + r) * DMODEL + h * DEPTH + c8;
            *(uint4*)&sKh[r * 72 + c8] = *(const uint4*)(Kh_ + go);
            *(uint4*)&sKl[r * 72 + c8] = *(const uint4*)(Kl_ + go);
        }
        __syncthreads();
#pragma unroll
        for (int ks = 0; ks < 2; ks++) {
            uint32_t ah[4], al[4];
            const int krow = ks * 16 + (lane & 7) + ((lane >> 4) << 3);
            const int mcol = wm + (((lane >> 3) & 1) << 3);
            ldsm4t(ah, &sKh[krow * 72 + mcol]);
            ldsm4t(al, &sKl[krow * 72 + mcol]);
            const int brow = ks * 16 + (lane & 15);
#pragma unroll
            for (int t = 0; t < 8; t++) {
                uint32_t beh[4], bel[4];
                const int bc = wn + t * 16 + (lane >> 4) * 8;
                ldsm4t(beh, &sEh[brow * 264 + bc]);
                ldsm4t(bel, &sEl[brow * 264 + bc]);
#pragma unroll
                for (int h2 = 0; h2 < 2; h2++) {
                    float* cc = c[t * 2 + h2];
                    mma16816(cc, ah, beh[h2 * 2], beh[h2 * 2 + 1]);
                    mma16816(cc, ah, bel[h2 * 2], bel[h2 * 2 + 1]);
                    mma16816(cc, al, beh[h2 * 2], beh[h2 * 2 + 1]);
                }
            }
        }
        __syncthreads();
    }
    const int g = lane >> 2, q = lane & 3;
    float* pb = part + ((size_t)(chunk * 64 + bh)) * 16384;
#pragma unroll
    for (int t = 0; t < 16; t++) {
        const int col = wn + t * 8 + q * 2;
        const int row = wm + g;
        *(float2*)&pb[row * 256 + col]       = make_float2(c[t][0], c[t][1]);
        *(float2*)&pb[(row + 8) * 256 + col] = make_float2(c[t][2], c[t][3]);
    }
}

// ---------------- proj V-path: C[r=256][d=64] = F^T @ V, per (bh, chunk) ----------------
__global__ __launch_bounds__(256, 2)
void projV(const bf16* __restrict__ Fh_, const bf16* __restrict__ Fl_,
           const bf16* __restrict__ Vh_, const bf16* __restrict__ Vl_,
           float* __restrict__ part) {
    __shared__ __align__(16) bf16 sFh[32 * 264], sFl[32 * 264];
    __shared__ __align__(16) bf16 sVh[32 * 72],  sVl[32 * 72];
    const int tid = threadIdx.x, lane = tid & 31, warp = tid >> 5;
    const int bh = blockIdx.x, b = bh >> 3, h = bh & 7, chunk = blockIdx.y;
    const int wm = (warp >> 1) * 64;
    const int wn = (warp & 1) * 32;

    float c[4][4][4];
#pragma unroll
    for (int i = 0; i < 4; i++)
#pragma unroll
        for (int j = 0; j < 4; j++)
#pragma unroll
            for (int k = 0; k < 4; k++) c[i][j][k] = 0.f;

    for (int it = 0; it < 16; it++) {
        const int nb = chunk * 512 + it * 32;
#pragma unroll
        for (int i = 0; i < 4; i++) {
            int u = tid + 256 * i, r = u >> 5, c8 = (u & 31) * 8;
            size_t go = ((size_t)h * NSEQ + nb + r) * RRANK + c8;
            *(uint4*)&sFh[r * 264 + c8] = *(const uint4*)(Fh_ + go);
            *(uint4*)&sFl[r * 264 + c8] = *(const uint4*)(Fl_ + go);
        }
        {
            int r = tid >> 3, c8 = (tid & 7) * 8;
            size_t go = ((size_t)b * NSEQ + nb + r) * DMODEL + h * DEPTH + c8;
            *(uint4*)&sVh[r * 72 + c8] = *(const uint4*)(Vh_ + go);
            *(uint4*)&sVl[r * 72 + c8] = *(const uint4*)(Vl_ + go);
        }
        __syncthreads();
#pragma unroll
        for (int ks = 0; ks < 2; ks++) {
            uint32_t ah[4][4], al[4][4];
#pragma unroll
            for (int mi = 0; mi < 4; mi++) {
                const int krow = ks * 16 + (lane & 7) + ((lane >> 4) << 3);
                const int mcol = wm + mi * 16 + (((lane >> 3) & 1) << 3);
                ldsm4t(ah[mi], &sFh[krow * 264 + mcol]);
                ldsm4t(al[mi], &sFl[krow * 264 + mcol]);
            }
            const int brow = ks * 16 + (lane & 15);
#pragma unroll
            for (int t = 0; t < 2; t++) {
                uint32_t bvh[4], bvl[4];
                const int bc = wn + t * 16 + (lane >> 4) * 8;
                ldsm4t(bvh, &sVh[brow * 72 + bc]);
                ldsm4t(bvl, &sVl[brow * 72 + bc]);
#pragma unroll
                for (int h2 = 0; h2 < 2; h2++) {
#pragma unroll
                    for (int mi = 0; mi < 4; mi++) {
                        float* cc = c[mi][t * 2 + h2];
                        mma16816(cc, ah[mi], bvh[h2 * 2], bvh[h2 * 2 + 1]);
                        mma16816(cc, ah[mi], bvl[h2 * 2], bvl[h2 * 2 + 1]);
                        mma16816(cc, al[mi], bvh[h2 * 2], bvh[h2 * 2 + 1]);
                    }
                }
            }
        }
        __syncthreads();
    }
    const int g = lane >> 2, q = lane & 3;
    float* pb = part + ((size_t)(chunk * 64 + bh)) * 16384;
#pragma unroll
    for (int mi = 0; mi < 4; mi++) {
        const int row = wm + mi * 16 + g;
#pragma unroll
        for (int nj = 0; nj < 4; nj++) {
            const int col = wn + nj * 8 + q * 2;
            *(float2*)&pb[row * 64 + col]       = make_float2(c[mi][nj][0], c[mi][nj][1]);
            *(float2*)&pb[(row + 8) * 64 + col] = make_float2(c[mi][nj][2], c[mi][nj][3]);
        }
    }
}

// ---------------- reduce partials -> bf16 hi/lo ----------------
__global__ void reduce_split(const float* __restrict__ part, bf16* __restrict__ oh,
                             bf16* __restrict__ ol) {
    int i = blockIdx.x * 256 + threadIdx.x;
    float s = 0.f;
#pragma unroll
    for (int c = 0; c < NCHUNK; c++) s += part[(size_t)c * 1048576 + i];
    bf16 h = __float2bfloat16(s);
    oh[i] = h;
    ol[i] = __float2bfloat16(s - __bfloat162float(h));
}

// ---------------- fused tensor-core attention ----------------
__global__ __launch_bounds__(256, 1)
void attn_mma(const bf16* __restrict__ qh_, const bf16* __restrict__ ql_,
              const bf16* __restrict__ kph_, const bf16* __restrict__ kpl_,
              const bf16* __restrict__ vph_, const bf16* __restrict__ vpl_,
              bf16* __restrict__ cath, bf16* __restrict__ catl) {
    extern __shared__ bf16 dsm[];
    bf16* sQh = dsm;
    bf16* sQl = sQh + 9216;
    bf16* sKh = sQl + 9216;
    bf16* sKl = sKh + 16896;
    bf16* sVh = sKl + 16896;
    bf16* sVl = sVh + 18432;

    const int tid = threadIdx.x, lane = tid & 31, warp = tid >> 5;
    const int m0 = blockIdx.x * 128;
    const int bh = blockIdx.y, b = bh >> 3, h = bh & 7;

#pragma unroll
    for (int i = 0; i < 4; i++) {
        int u = tid + 256 * i, r = u >> 3, c8 = (u & 7) * 8;
        size_t go = ((size_t)(b * NSEQ + m0 + r)) * DMODEL + h * DEPTH + c8;
        *(uint4*)&sQh[r * 72 + c8] = *(const uint4*)(qh_ + go);
        *(uint4*)&sQl[r * 72 + c8] = *(const uint4*)(ql_ + go);
    }
#pragma unroll
    for (int i = 0; i < 8; i++) {
        int u = tid + 256 * i, r = u >> 5, c8 = (u & 31) * 8;
        size_t go = (size_t)bh * 16384 + (size_t)r * 256 + c8;
        *(uint4*)&sKh[r * 264 + c8] = *(const uint4*)(kph_ + go);
        *(uint4*)&sKl[r * 264 + c8] = *(const uint4*)(kpl_ + go);
    }
#pragma unroll
    for (int i = 0; i < 8; i++) {
        int u = tid + 256 * i, r = u >> 3, c8 = (u & 7) * 8;
        size_t go = (size_t)bh * 16384 + (size_t)r * 64 + c8;
        *(uint4*)&sVh[r * 72 + c8] = *(const uint4*)(vph_ + go);
        *(uint4*)&sVl[r * 72 + c8] = *(const uint4*)(vpl_ + go);
    }
    __syncthreads();

    const int wm = warp * 16;
    float c[32][4];
#pragma unroll
    for (int t = 0; t < 32; t++)
#pragma unroll
        for (int j = 0; j < 4; j++) c[t][j] = 0.f;

#pragma unroll
    for (int kd = 0; kd < 4; kd++) {
        uint32_t ah4[4], al4[4];
        const int ar = wm + (lane & 15);
        const int ac = kd * 16 + (lane >> 4) * 8;
        ldsm4(ah4, &sQh[ar * 72 + ac]);
        ldsm4(al4, &sQl[ar * 72 + ac]);
        const int brow = kd * 16 + (lane & 15);
#pragma unroll
        for (int t = 0; t < 16; t++) {
            uint32_t bh4[4], bl4[4];
            const int bc = t * 16 + (lane >> 4) * 8;
            ldsm4t(bh4, &sKh[brow * 264 + bc]);
            ldsm4t(bl4, &sKl[brow * 264 + bc]);
#pragma unroll
            for (int h2 = 0; h2 < 2; h2++) {
                float* cc = c[t * 2 + h2];
                mma16816(cc, ah4, bh4[h2 * 2], bh4[h2 * 2 + 1]);
                mma16816(cc, ah4, bl4[h2 * 2], bl4[h2 * 2 + 1]);
                mma16816(cc, al4, bh4[h2 * 2], bh4[h2 * 2 + 1]);
            }
        }
    }

#pragma unroll
    for (int t = 0; t < 32; t++)
#pragma unroll
        for (int j = 0; j < 4; j++) c[t][j] *= 0.125f;

    float mx0 = -1e30f, mx1 = -1e30f;
#pragma unroll
    for (int t = 0; t < 32; t++) {
        mx0 = fmaxf(mx0, fmaxf(c[t][0], c[t][1]));
        mx1 = fmaxf(mx1, fmaxf(c[t][2], c[t][3]));
    }
    mx0 = fmaxf(mx0, __shfl_xor_sync(0xffffffffu, mx0, 1));
    mx0 = fmaxf(mx0, __shfl_xor_sync(0xffffffffu, mx0, 2));
    mx1 = fmaxf(mx1, __shfl_xor_sync(0xffffffffu, mx1, 1));
    mx1 = fmaxf(mx1, __shfl_xor_sync(0xffffffffu, mx1, 2));

    float s0 = 0.f, s1 = 0.f;
#pragma unroll
    for (int t = 0; t < 32; t++) {
        c[t][0] = __expf(c[t][0] - mx0); s0 += c[t][0];
        c[t][1] = __expf(c[t][1] - mx0); s0 += c[t][1];
        c[t][2] = __expf(c[t][2] - mx1); s1 += c[t][2];
        c[t][3] = __expf(c[t][3] - mx1); s1 += c[t][3];
    }
    s0 += __shfl_xor_sync(0xffffffffu, s0, 1);
    s0 += __shfl_xor_sync(0xffffffffu, s0, 2);
    s1 += __shfl_xor_sync(0xffffffffu, s1, 1);
    s1 += __shfl_xor_sync(0xffffffffu, s1, 2);
    const float inv0 = 1.0f / s0, inv1 = 1.0f / s1;

    uint32_t phi[32][2], plo[32][2];
#pragma unroll
    for (int t = 0; t < 32; t++) {
        split2(c[t][0] * inv0, c[t][1] * inv0, phi[t][0], plo[t][0]);
        split2(c[t][2] * inv1, c[t][3] * inv1, phi[t][1], plo[t][1]);
    }

    float o[8][4];
#pragma unroll
    for (int j = 0; j < 8; j++)
#pragma unroll
        for (int k = 0; k < 4; k++) o[j][k] = 0.f;

#pragma unroll
    for (int rk = 0; rk < 16; rk++) {
        uint32_t pah[4] = { phi[2 * rk][0], phi[2 * rk][1], phi[2 * rk + 1][0], phi[2 * rk + 1][1] };
        uint32_t pal[4] = { plo[2 * rk][0], plo[2 * rk][1], plo[2 * rk + 1][0], plo[2 * rk + 1][1] };
        const int brow = rk * 16 + (lane & 15);
#pragma unroll
        for (int db = 0; db < 4; db++) {
            uint32_t vh4[4], vl4[4];
            const int bc = db * 16 + (lane >> 4) * 8;
            ldsm4t(vh4, &sVh[brow * 72 + bc]);
            ldsm4t(vl4, &sVl[brow * 72 + bc]);
#pragma unroll
            for (int h2 = 0; h2 < 2; h2++) {
                float* oo = o[db * 2 + h2];
                mma16816(oo, pah, vh4[h2 * 2], vh4[h2 * 2 + 1]);
                mma16816(oo, pal, vh4[h2 * 2], vh4[h2 * 2 + 1]);
                mma16816(oo, pah, vl4[h2 * 2], vl4[h2 * 2 + 1]);
            }
        }
    }

    const int g = lane >> 2, q = lane & 3;
    const size_t row0 = (size_t)(b * NSEQ + m0 + wm + g);
#pragma unroll
    for (int j = 0; j < 8; j++) {
        const int col = h * DEPTH + j * 8 + q * 2;
        uint32_t hp, lp;
        split2(o[j][0], o[j][1], hp, lp);
        *(uint32_t*)&cath[row0 * DMODEL + col] = hp;
        *(uint32_t*)&catl[row0 * DMODEL + col] = lp;
        split2(o[j][2], o[j][3], hp, lp);
        *(uint32_t*)&cath[(row0 + 8) * DMODEL + col] = hp;
        *(uint32_t*)&catl[(row0 + 8) * DMODEL + col] = lp;
    }
}

// ---------------- launch ----------------
extern "C" void kernel_launch(void* const* d_in, const int* in_sizes, int n_in,
                              void* d_out, int out_size) {
    const float* x  = (const float*)d_in[0];
    const float* wq = (const float*)d_in[1];
    const float* wk = (const float*)d_in[2];
    const float* wv = (const float*)d_in[3];
    const float* E  = (const float*)d_in[4];
    const float* F  = (const float*)d_in[5];
    const float* wd = (const float*)d_in[6];
    const float* bd = (const float*)d_in[7];
    float* out = (float*)d_out;

    float* gpart;
    bf16 *gxh, *gxl, *gwh, *gwl, *gqh, *gql, *gkh, *gkl, *gvh, *gvl;
    bf16 *gEh, *gEl, *gFh, *gFl, *gkpth, *gkptl, *gvph, *gvpl, *gcath, *gcatl;
    cudaGetSymbolAddress((void**)&gpart, g_part);
    cudaGetSymbolAddress((void**)&gxh, g_xh);   cudaGetSymbolAddress((void**)&gxl, g_xl);
    cudaGetSymbolAddress((void**)&gwh, g_wh);   cudaGetSymbolAddress((void**)&gwl, g_wl);
    cudaGetSymbolAddress((void**)&gqh, g_qh);   cudaGetSymbolAddress((void**)&gql, g_ql);
    cudaGetSymbolAddress((void**)&gkh, g_kh);   cudaGetSymbolAddress((void**)&gkl, g_kl);
    cudaGetSymbolAddress((void**)&gvh, g_vh);   cudaGetSymbolAddress((void**)&gvl, g_vl);
    cudaGetSymbolAddress((void**)&gEh, g_Eh);   cudaGetSymbolAddress((void**)&gEl, g_El);
    cudaGetSymbolAddress((void**)&gFh, g_Fh);   cudaGetSymbolAddress((void**)&gFl, g_Fl);
    cudaGetSymbolAddress((void**)&gkpth, g_kpth); cudaGetSymbolAddress((void**)&gkptl, g_kptl);
    cudaGetSymbolAddress((void**)&gvph, g_vph); cudaGetSymbolAddress((void**)&gvpl, g_vpl);
    cudaGetSymbolAddress((void**)&gcath, g_cath); cudaGetSymbolAddress((void**)&gcatl, g_catl);

    cvt_split<<<MROWS * DMODEL / 256, 256>>>(x, gxh, gxl, MROWS * DMODEL);
    cvt_split<<<1024, 256>>>(wq, gwh + 0 * 262144, gwl + 0 * 262144, 262144);
    cvt_split<<<1024, 256>>>(wk, gwh + 1 * 262144, gwl + 1 * 262144, 262144);
    cvt_split<<<1024, 256>>>(wv, gwh + 2 * 262144, gwl + 2 * 262144, 262144);
    cvt_split<<<1024, 256>>>(wd, gwh + 3 * 262144, gwl + 3 * 262144, 262144);
    cvt_split<<<HEADS * NSEQ * RRANK / 256, 256>>>(E, gEh, gEl, HEADS * NSEQ * RRANK);
    cvt_split<<<HEADS * NSEQ * RRANK / 256, 256>>>(F, gFh, gFl, HEADS * NSEQ * RRANK);

    cudaFuncSetAttribute(mma_gemm, cudaFuncAttributeMaxDynamicSharedMemorySize, GEMM_SMEM);

    dim3 gg(DMODEL / 128, MROWS / 128);
    mma_gemm<<<gg, 256, GEMM_SMEM>>>(gxh, gxl, gwh + 0 * 262144, gwl + 0 * 262144, nullptr,
                                     nullptr, gqh, gql, MROWS, DMODEL, DMODEL);
    mma_gemm<<<gg, 256, GEMM_SMEM>>>(gxh, gxl, gwh + 1 * 262144, gwl + 1 * 262144, nullptr,
                                     nullptr, gkh, gkl, MROWS, DMODEL, DMODEL);
    mma_gemm<<<gg, 256, GEMM_SMEM>>>(gxh, gxl, gwh + 2 * 262144, gwl + 2 * 262144, nullptr,
                                     nullptr, gvh, gvl, MROWS, DMODEL, DMODEL);

    projK<<<dim3(BATCH * HEADS, NCHUNK), 256>>>(gkh, gkl, gEh, gEl, gpart);
    reduce_split<<<1048576 / 256, 256>>>(gpart, gkpth, gkptl);
    projV<<<dim3(BATCH * HEADS, NCHUNK), 256>>>(gFh, gFl, gvh, gvl, gpart);
    reduce_split<<<1048576 / 256, 256>>>(gpart, gvph, gvpl);

    cudaFuncSetAttribute(attn_mma, cudaFuncAttributeMaxDynamicSharedMemorySize, 178176);
    attn_mma<<<dim3(NSEQ / 128, BATCH * HEADS), 256, 178176>>>(
        gqh, gql, gkpth, gkptl, gvph, gvpl, gcath, gcatl);

    mma_gemm<<<gg, 256, GEMM_SMEM>>>(gcath, gcatl, gwh + 3 * 262144, gwl + 3 * 262144, bd,
                                     out, nullptr, nullptr, MROWS, DMODEL, DMODEL);
}

// round 17
// speedup vs baseline: 3.9031x; 1.3314x over previous
#include <cuda_runtime.h>
#include <cuda_fp16.h>
#include <cstddef>
#include <cstdint>

typedef __half hf;

#define NSEQ   4096
#define BATCH  8
#define DMODEL 512
#define HEADS  8
#define RRANK  256
#define DEPTH  64
#define MROWS  32768
#define NCHUNK 8

// ---------------- scratch (static device allocations only) ----------------
__device__ float g_part[8388608];
__device__ hf g_xh[16777216], g_xl[16777216];
__device__ hf g_wh[1048576];                         // wq|wk|wv|wd hi slabs (no lo needed: B-side)
__device__ hf g_qh[16777216], g_ql[16777216];
__device__ hf g_kh[16777216], g_kl[16777216];
__device__ hf g_vh[16777216];                        // V is B-side only -> hi only
__device__ hf g_Eh[8388608];                         // E is B-side only -> hi only
__device__ hf g_Fh[8388608],  g_Fl[8388608];         // F is A-side -> hi+lo
__device__ hf g_kpth[1048576];                       // kp^T, B-side -> hi only
__device__ hf g_vph[1048576];                        // vp, B-side -> hi only
__device__ hf g_cath[16777216], g_catl[16777216];    // cat is A-side -> hi+lo

// ---------------- fp32 -> fp16 hi/lo split ----------------
__global__ void cvt_split(const float* __restrict__ in, hf* __restrict__ hi,
                          hf* __restrict__ lo, int n) {
    int i = blockIdx.x * 256 + threadIdx.x;
    if (i < n) {
        float v = in[i];
        hf h = __float2half_rn(v);
        hi[i] = h;
        lo[i] = __float2half_rn(v - __half2float(h));
    }
}
__global__ void cvt_hi(const float* __restrict__ in, hf* __restrict__ hi, int n) {
    int i = blockIdx.x * 256 + threadIdx.x;
    if (i < n) hi[i] = __float2half_rn(in[i]);
}

// ---------------- mma helpers ----------------
__device__ __forceinline__ void ldsm4(uint32_t r[4], const void* p) {
    uint32_t a = (uint32_t)__cvta_generic_to_shared(p);
    asm volatile("ldmatrix.sync.aligned.m8n8.x4.shared.b16 {%0,%1,%2,%3}, [%4];"
                 : "=r"(r[0]), "=r"(r[1]), "=r"(r[2]), "=r"(r[3]) : "r"(a));
}
__device__ __forceinline__ void ldsm4t(uint32_t r[4], const void* p) {
    uint32_t a = (uint32_t)__cvta_generic_to_shared(p);
    asm volatile("ldmatrix.sync.aligned.m8n8.x4.trans.shared.b16 {%0,%1,%2,%3}, [%4];"
                 : "=r"(r[0]), "=r"(r[1]), "=r"(r[2]), "=r"(r[3]) : "r"(a));
}
__device__ __forceinline__ void mma16816(float c[4], const uint32_t a[4],
                                         uint32_t b0, uint32_t b1) {
    asm volatile("mma.sync.aligned.m16n8k16.row.col.f32.f16.f16.f32 "
                 "{%0,%1,%2,%3},{%4,%5,%6,%7},{%8,%9},{%0,%1,%2,%3};"
                 : "+f"(c[0]), "+f"(c[1]), "+f"(c[2]), "+f"(c[3])
                 : "r"(a[0]), "r"(a[1]), "r"(a[2]), "r"(a[3]), "r"(b0), "r"(b1));
}
__device__ __forceinline__ uint32_t packh(hf a, hf b) {
    __half2 t; t.x = a; t.y = b;
    return *reinterpret_cast<uint32_t*>(&t);
}
__device__ __forceinline__ void split2(float v0, float v1, uint32_t& hp, uint32_t& lp) {
    hf h0 = __float2half_rn(v0), h1 = __float2half_rn(v1);
    hp = packh(h0, h1);
    lp = packh(__float2half_rn(v0 - __half2float(h0)),
               __float2half_rn(v1 - __half2float(h1)));
}
__device__ __forceinline__ void cpa16(void* smem_dst, const void* gsrc) {
    uint32_t d = (uint32_t)__cvta_generic_to_shared(smem_dst);
    asm volatile("cp.async.cg.shared.global [%0], [%1], 16;" :: "r"(d), "l"(gsrc));
}
__device__ __forceinline__ void cpa_commit() {
    asm volatile("cp.async.commit_group;");
}
template<int N>
__device__ __forceinline__ void cpa_wait() {
    asm volatile("cp.async.wait_group %0;" :: "n"(N));
}

// ---------------- cp.async double-buffered fp16 2-term GEMM ----------------
// C = Ah@Bh + Al@Bh  (drop A@Bl: ~2^-11 relative). BM=128, BN=128, BK=32, 256 thr.
// Dynamic smem (halves): sAh[2][5120] | sAl[2][5120] | sBh[2][4352]
#define SM_AH 0
#define SM_AL 10240
#define SM_BH 20480
#define GEMM_SMEM 58368
__global__ __launch_bounds__(256, 2)
void mma_gemm(const hf* __restrict__ Ahi_, const hf* __restrict__ Alo_,
              const hf* __restrict__ Bhi_,
              const float* __restrict__ bias, float* __restrict__ C,
              hf* __restrict__ Chi, hf* __restrict__ Clo,
              int M, int K, int Nn) {
    extern __shared__ hf smp[];

    const int tid  = threadIdx.x;
    const int lane = tid & 31, warp = tid >> 5;
    const int wm = (warp >> 2) * 64;
    const int wn = (warp & 3) * 32;
    const int bRow = blockIdx.y * 128, bCol = blockIdx.x * 128;

    float acc[4][4][4];
#pragma unroll
    for (int i = 0; i < 4; i++)
#pragma unroll
        for (int j = 0; j < 4; j++)
#pragma unroll
            for (int c = 0; c < 4; c++) acc[i][j][c] = 0.f;

    const int arow = tid >> 2, acol = (tid & 3) * 8;
    const int brow = tid >> 4, bcol = (tid & 15) * 8;
    const int nIter = K / 32;

    auto prefetch = [&](int st, int kt) {
        hf* sAh = smp + SM_AH + st * 5120;
        hf* sAl = smp + SM_AL + st * 5120;
        hf* sBh = smp + SM_BH + st * 4352;
#pragma unroll
        for (int rr = 0; rr < 2; rr++) {
            int r = arow + rr * 64;
            size_t go = (size_t)(bRow + r) * K + kt + acol;
            cpa16(&sAh[r * 40 + acol], Ahi_ + go);
            cpa16(&sAl[r * 40 + acol], Alo_ + go);
        }
#pragma unroll
        for (int rr = 0; rr < 2; rr++) {
            int r = brow + rr * 16;
            size_t go = (size_t)(kt + r) * Nn + bCol + bcol;
            cpa16(&sBh[r * 136 + bcol], Bhi_ + go);
        }
        cpa_commit();
    };

    prefetch(0, 0);
    if (nIter > 1) prefetch(1, 32);

    for (int it = 0; it < nIter; it++) {
        const int st = it & 1;
        if (it + 1 < nIter) cpa_wait<1>(); else cpa_wait<0>();
        __syncthreads();

        hf* sAh = smp + SM_AH + st * 5120;
        hf* sAl = smp + SM_AL + st * 5120;
        hf* sBh = smp + SM_BH + st * 4352;

#pragma unroll
        for (int ks = 0; ks < 2; ks++) {
            uint32_t ah[4][4], al[4][4];
            const int ar = wm + (lane & 15);
            const int ac = ks * 16 + (lane >> 4) * 8;
#pragma unroll
            for (int mi = 0; mi < 4; mi++) {
                ldsm4(ah[mi], &sAh[(ar + mi * 16) * 40 + ac]);
                ldsm4(al[mi], &sAl[(ar + mi * 16) * 40 + ac]);
            }
            const int br = ks * 16 + (lane & 15);
#pragma unroll
            for (int jp = 0; jp < 2; jp++) {
                uint32_t bh[4];
                const int bc = wn + jp * 16 + (lane >> 4) * 8;
                ldsm4t(bh, &sBh[br * 136 + bc]);
#pragma unroll
                for (int h = 0; h < 2; h++) {
#pragma unroll
                    for (int mi = 0; mi < 4; mi++) {
                        float* a4 = acc[mi][jp * 2 + h];
                        mma16816(a4, ah[mi], bh[h * 2], bh[h * 2 + 1]);
                        mma16816(a4, al[mi], bh[h * 2], bh[h * 2 + 1]);
                    }
                }
            }
        }
        __syncthreads();
        if (it + 2 < nIter) prefetch(st, (it + 2) * 32);
    }

    const int gid = lane >> 2, qid = lane & 3;
#pragma unroll
    for (int mi = 0; mi < 4; mi++) {
        const int row = bRow + wm + mi * 16 + gid;
#pragma unroll
        for (int nj = 0; nj < 4; nj++) {
            const int col = bCol + wn + nj * 8 + qid * 2;
            if (Chi) {
                uint32_t hp, lp;
                split2(acc[mi][nj][0], acc[mi][nj][1], hp, lp);
                *(uint32_t*)&Chi[(size_t)row * Nn + col] = hp;
                if (Clo) *(uint32_t*)&Clo[(size_t)row * Nn + col] = lp;
                split2(acc[mi][nj][2], acc[mi][nj][3], hp, lp);
                *(uint32_t*)&Chi[(size_t)(row + 8) * Nn + col] = hp;
                if (Clo) *(uint32_t*)&Clo[(size_t)(row + 8) * Nn + col] = lp;
            } else {
                float b0 = 0.f, b1 = 0.f;
                if (bias) { b0 = bias[col]; b1 = bias[col + 1]; }
                *(float2*)&C[(size_t)row * Nn + col] =
                    make_float2(acc[mi][nj][0] + b0, acc[mi][nj][1] + b1);
                *(float2*)&C[(size_t)(row + 8) * Nn + col] =
                    make_float2(acc[mi][nj][2] + b0, acc[mi][nj][3] + b1);
            }
        }
    }
}

// ---------------- proj K-path: C[d=64][r=256] = K^T @ E, per (bh, chunk) ----------------
// A = K^T (hi+lo), B = E (hi only).
__global__ __launch_bounds__(256, 2)
void projK(const hf* __restrict__ Kh_, const hf* __restrict__ Kl_,
           const hf* __restrict__ Eh_, float* __restrict__ part) {
    __shared__ __align__(16) hf sEh[32 * 264];
    __shared__ __align__(16) hf sKh[32 * 72], sKl[32 * 72];
    const int tid = threadIdx.x, lane = tid & 31, warp = tid >> 5;
    const int bh = blockIdx.x, b = bh >> 3, h = bh & 7, chunk = blockIdx.y;
    const int wm = (warp & 3) * 16;
    const int wn = (warp >> 2) * 128;

    float c[16][4];
#pragma unroll
    for (int t = 0; t < 16; t++)
#pragma unroll
        for (int j = 0; j < 4; j++) c[t][j] = 0.f;

    for (int it = 0; it < 16; it++) {
        const int nb = chunk * 512 + it * 32;
#pragma unroll
        for (int i = 0; i < 4; i++) {
            int u = tid + 256 * i, r = u >> 5, c8 = (u & 31) * 8;
            size_t go = ((size_t)h * NSEQ + nb + r) * RRANK + c8;
            *(uint4*)&sEh[r * 264 + c8] = *(const uint4*)(Eh_ + go);
        }
        {
            int r = tid >> 3, c8 = (tid & 7) * 8;
            size_t go = ((size_t)b * NSEQ + nb + r) * DMODEL + h * DEPTH + c8;
            *(uint4*)&sKh[r * 72 + c8] = *(const uint4*)(Kh_ + go);
            *(uint4*)&sKl[r * 72 + c8] = *(const uint4*)(Kl_ + go);
        }
        __syncthreads();
#pragma unroll
        for (int ks = 0; ks < 2; ks++) {
            uint32_t ah[4], al[4];
            const int krow = ks * 16 + (lane & 7) + ((lane >> 4) << 3);
            const int mcol = wm + (((lane >> 3) & 1) << 3);
            ldsm4t(ah, &sKh[krow * 72 + mcol]);
            ldsm4t(al, &sKl[krow * 72 + mcol]);
            const int brow = ks * 16 + (lane & 15);
#pragma unroll
            for (int t = 0; t < 8; t++) {
                uint32_t beh[4];
                const int bc = wn + t * 16 + (lane >> 4) * 8;
                ldsm4t(beh, &sEh[brow * 264 + bc]);
#pragma unroll
                for (int h2 = 0; h2 < 2; h2++) {
                    float* cc = c[t * 2 + h2];
                    mma16816(cc, ah, beh[h2 * 2], beh[h2 * 2 + 1]);
                    mma16816(cc, al, beh[h2 * 2], beh[h2 * 2 + 1]);
                }
            }
        }
        __syncthreads();
    }
    const int g = lane >> 2, q = lane & 3;
    float* pb = part + ((size_t)(chunk * 64 + bh)) * 16384;
#pragma unroll
    for (int t = 0; t < 16; t++) {
        const int col = wn + t * 8 + q * 2;
        const int row = wm + g;
        *(float2*)&pb[row * 256 + col]       = make_float2(c[t][0], c[t][1]);
        *(float2*)&pb[(row + 8) * 256 + col] = make_float2(c[t][2], c[t][3]);
    }
}

// ---------------- proj V-path: C[r=256][d=64] = F^T @ V, per (bh, chunk) ----------------
// A = F^T (hi+lo), B = V (hi only).
__global__ __launch_bounds__(256, 2)
void projV(const hf* __restrict__ Fh_, const hf* __restrict__ Fl_,
           const hf* __restrict__ Vh_, float* __restrict__ part) {
    __shared__ __align__(16) hf sFh[32 * 264], sFl[32 * 264];
    __shared__ __align__(16) hf sVh[32 * 72];
    const int tid = threadIdx.x, lane = tid & 31, warp = tid >> 5;
    const int bh = blockIdx.x, b = bh >> 3, h = bh & 7, chunk = blockIdx.y;
    const int wm = (warp >> 1) * 64;
    const int wn = (warp & 1) * 32;

    float c[4][4][4];
#pragma unroll
    for (int i = 0; i < 4; i++)
#pragma unroll
        for (int j = 0; j < 4; j++)
#pragma unroll
            for (int k = 0; k < 4; k++) c[i][j][k] = 0.f;

    for (int it = 0; it < 16; it++) {
        const int nb = chunk * 512 + it * 32;
#pragma unroll
        for (int i = 0; i < 4; i++) {
            int u = tid + 256 * i, r = u >> 5, c8 = (u & 31) * 8;
            size_t go = ((size_t)h * NSEQ + nb + r) * RRANK + c8;
            *(uint4*)&sFh[r * 264 + c8] = *(const uint4*)(Fh_ + go);
            *(uint4*)&sFl[r * 264 + c8] = *(const uint4*)(Fl_ + go);
        }
        {
            int r = tid >> 3, c8 = (tid & 7) * 8;
            size_t go = ((size_t)b * NSEQ + nb + r) * DMODEL + h * DEPTH + c8;
            *(uint4*)&sVh[r * 72 + c8] = *(const uint4*)(Vh_ + go);
        }
        __syncthreads();
#pragma unroll
        for (int ks = 0; ks < 2; ks++) {
            uint32_t ah[4][4], al[4][4];
#pragma unroll
            for (int mi = 0; mi < 4; mi++) {
                const int krow = ks * 16 + (lane & 7) + ((lane >> 4) << 3);
                const int mcol = wm + mi * 16 + (((lane >> 3) & 1) << 3);
                ldsm4t(ah[mi], &sFh[krow * 264 + mcol]);
                ldsm4t(al[mi], &sFl[krow * 264 + mcol]);
            }
            const int brow = ks * 16 + (lane & 15);
#pragma unroll
            for (int t = 0; t < 2; t++) {
                uint32_t bvh[4];
                const int bc = wn + t * 16 + (lane >> 4) * 8;
                ldsm4t(bvh, &sVh[brow * 72 + bc]);
#pragma unroll
                for (int h2 = 0; h2 < 2; h2++) {
#pragma unroll
                    for (int mi = 0; mi < 4; mi++) {
                        float* cc = c[mi][t * 2 + h2];
                        mma16816(cc, ah[mi], bvh[h2 * 2], bvh[h2 * 2 + 1]);
                        mma16816(cc, al[mi], bvh[h2 * 2], bvh[h2 * 2 + 1]);
                    }
                }
            }
        }
        __syncthreads();
    }
    const int g = lane >> 2, q = lane & 3;
    float* pb = part + ((size_t)(chunk * 64 + bh)) * 16384;
#pragma unroll
    for (int mi = 0; mi < 4; mi++) {
        const int row = wm + mi * 16 + g;
#pragma unroll
        for (int nj = 0; nj < 4; nj++) {
            const int col = wn + nj * 8 + q * 2;
            *(float2*)&pb[row * 64 + col]       = make_float2(c[mi][nj][0], c[mi][nj][1]);
            *(float2*)&pb[(row + 8) * 64 + col] = make_float2(c[mi][nj][2], c[mi][nj][3]);
        }
    }
}

// ---------------- reduce partials -> fp16 hi ----------------
__global__ void reduce_hi(const float* __restrict__ part, hf* __restrict__ oh) {
    int i = blockIdx.x * 256 + threadIdx.x;
    float s = 0.f;
#pragma unroll
    for (int c = 0; c < NCHUNK; c++) s += part[(size_t)c * 1048576 + i];
    oh[i] = __float2half_rn(s);
}

// ---------------- fused tensor-core attention (fp16 2-term) ----------------
// Q hi+lo (A), kp^T hi (B), P hi+lo (A), vp hi (B).
__global__ __launch_bounds__(256, 1)
void attn_mma(const hf* __restrict__ qh_, const hf* __restrict__ ql_,
              const hf* __restrict__ kph_, const hf* __restrict__ vph_,
              hf* __restrict__ cath, hf* __restrict__ catl) {
    extern __shared__ hf dsm[];
    hf* sQh = dsm;               // 128 x 72
    hf* sQl = sQh + 9216;
    hf* sKh = sQl + 9216;        // 64 x 264
    hf* sVh = sKh + 16896;       // 256 x 72

    const int tid = threadIdx.x, lane = tid & 31, warp = tid >> 5;
    const int m0 = blockIdx.x * 128;
    const int bh = blockIdx.y, b = bh >> 3, h = bh & 7;

#pragma unroll
    for (int i = 0; i < 4; i++) {
        int u = tid + 256 * i, r = u >> 3, c8 = (u & 7) * 8;
        size_t go = ((size_t)(b * NSEQ + m0 + r)) * DMODEL + h * DEPTH + c8;
        *(uint4*)&sQh[r * 72 + c8] = *(const uint4*)(qh_ + go);
        *(uint4*)&sQl[r * 72 + c8] = *(const uint4*)(ql_ + go);
    }
#pragma unroll
    for (int i = 0; i < 8; i++) {
        int u = tid + 256 * i, r = u >> 5, c8 = (u & 31) * 8;
        size_t go = (size_t)bh * 16384 + (size_t)r * 256 + c8;
        *(uint4*)&sKh[r * 264 + c8] = *(const uint4*)(kph_ + go);
    }
#pragma unroll
    for (int i = 0; i < 8; i++) {
        int u = tid + 256 * i, r = u >> 3, c8 = (u & 7) * 8;
        size_t go = (size_t)bh * 16384 + (size_t)r * 64 + c8;
        *(uint4*)&sVh[r * 72 + c8] = *(const uint4*)(vph_ + go);
    }
    __syncthreads();

    const int wm = warp * 16;
    float c[32][4];
#pragma unroll
    for (int t = 0; t < 32; t++)
#pragma unroll
        for (int j = 0; j < 4; j++) c[t][j] = 0.f;

#pragma unroll
    for (int kd = 0; kd < 4; kd++) {
        uint32_t ah4[4], al4[4];
        const int ar = wm + (lane & 15);
        const int ac = kd * 16 + (lane >> 4) * 8;
        ldsm4(ah4, &sQh[ar * 72 + ac]);
        ldsm4(al4, &sQl[ar * 72 + ac]);
        const int brow = kd * 16 + (lane & 15);
#pragma unroll
        for (int t = 0; t < 16; t++) {
            uint32_t bh4[4];
            const int bc = t * 16 + (lane >> 4) * 8;
            ldsm4t(bh4, &sKh[brow * 264 + bc]);
#pragma unroll
            for (int h2 = 0; h2 < 2; h2++) {
                float* cc = c[t * 2 + h2];
                mma16816(cc, ah4, bh4[h2 * 2], bh4[h2 * 2 + 1]);
                mma16816(cc, al4, bh4[h2 * 2], bh4[h2 * 2 + 1]);
            }
        }
    }

#pragma unroll
    for (int t = 0; t < 32; t++)
#pragma unroll
        for (int j = 0; j < 4; j++) c[t][j] *= 0.125f;

    float mx0 = -1e30f, mx1 = -1e30f;
#pragma unroll
    for (int t = 0; t < 32; t++) {
        mx0 = fmaxf(mx0, fmaxf(c[t][0], c[t][1]));
        mx1 = fmaxf(mx1, fmaxf(c[t][2], c[t][3]));
    }
    mx0 = fmaxf(mx0, __shfl_xor_sync(0xffffffffu, mx0, 1));
    mx0 = fmaxf(mx0, __shfl_xor_sync(0xffffffffu, mx0, 2));
    mx1 = fmaxf(mx1, __shfl_xor_sync(0xffffffffu, mx1, 1));
    mx1 = fmaxf(mx1, __shfl_xor_sync(0xffffffffu, mx1, 2));

    float s0 = 0.f, s1 = 0.f;
#pragma unroll
    for (int t = 0; t < 32; t++) {
        c[t][0] = __expf(c[t][0] - mx0); s0 += c[t][0];
        c[t][1] = __expf(c[t][1] - mx0); s0 += c[t][1];
        c[t][2] = __expf(c[t][2] - mx1); s1 += c[t][2];
        c[t][3] = __expf(c[t][3] - mx1); s1 += c[t][3];
    }
    s0 += __shfl_xor_sync(0xffffffffu, s0, 1);
    s0 += __shfl_xor_sync(0xffffffffu, s0, 2);
    s1 += __shfl_xor_sync(0xffffffffu, s1, 1);
    s1 += __shfl_xor_sync(0xffffffffu, s1, 2);
    const float inv0 = 1.0f / s0, inv1 = 1.0f / s1;

    uint32_t phi[32][2], plo[32][2];
#pragma unroll
    for (int t = 0; t < 32; t++) {
        split2(c[t][0] * inv0, c[t][1] * inv0, phi[t][0], plo[t][0]);
        split2(c[t][2] * inv1, c[t][3] * inv1, phi[t][1], plo[t][1]);
    }

    float o[8][4];
#pragma unroll
    for (int j = 0; j < 8; j++)
#pragma unroll
        for (int k = 0; k < 4; k++) o[j][k] = 0.f;

#pragma unroll
    for (int rk = 0; rk < 16; rk++) {
        uint32_t pah[4] = { phi[2 * rk][0], phi[2 * rk][1], phi[2 * rk + 1][0], phi[2 * rk + 1][1] };
        uint32_t pal[4] = { plo[2 * rk][0], plo[2 * rk][1], plo[2 * rk + 1][0], plo[2 * rk + 1][1] };
        const int brow = rk * 16 + (lane & 15);
#pragma unroll
        for (int db = 0; db < 4; db++) {
            uint32_t vh4[4];
            const int bc = db * 16 + (lane >> 4) * 8;
            ldsm4t(vh4, &sVh[brow * 72 + bc]);
#pragma unroll
            for (int h2 = 0; h2 < 2; h2++) {
                float* oo = o[db * 2 + h2];
                mma16816(oo, pah, vh4[h2 * 2], vh4[h2 * 2 + 1]);
                mma16816(oo, pal, vh4[h2 * 2], vh4[h2 * 2 + 1]);
            }
        }
    }

    const int g = lane >> 2, q = lane & 3;
    const size_t row0 = (size_t)(b * NSEQ + m0 + wm + g);
#pragma unroll
    for (int j = 0; j < 8; j++) {
        const int col = h * DEPTH + j * 8 + q * 2;
        uint32_t hp, lp;
        split2(o[j][0], o[j][1], hp, lp);
        *(uint32_t*)&cath[row0 * DMODEL + col] = hp;
        *(uint32_t*)&catl[row0 * DMODEL + col] = lp;
        split2(o[j][2], o[j][3], hp, lp);
        *(uint32_t*)&cath[(row0 + 8) * DMODEL + col] = hp;
        *(uint32_t*)&catl[(row0 + 8) * DMODEL + col] = lp;
    }
}
#define ATTN_SMEM ((9216 + 9216 + 16896 + 18432) * 2)

// ---------------- launch ----------------
extern "C" void kernel_launch(void* const* d_in, const int* in_sizes, int n_in,
                              void* d_out, int out_size) {
    const float* x  = (const float*)d_in[0];
    const float* wq = (const float*)d_in[1];
    const float* wk = (const float*)d_in[2];
    const float* wv = (const float*)d_in[3];
    const float* E  = (const float*)d_in[4];
    const float* F  = (const float*)d_in[5];
    const float* wd = (const float*)d_in[6];
    const float* bd = (const float*)d_in[7];
    float* out = (float*)d_out;

    float* gpart;
    hf *gxh, *gxl, *gwh, *gqh, *gql, *gkh, *gkl, *gvh;
    hf *gEh, *gFh, *gFl, *gkpth, *gvph, *gcath, *gcatl;
    cudaGetSymbolAddress((void**)&gpart, g_part);
    cudaGetSymbolAddress((void**)&gxh, g_xh);   cudaGetSymbolAddress((void**)&gxl, g_xl);
    cudaGetSymbolAddress((void**)&gwh, g_wh);
    cudaGetSymbolAddress((void**)&gqh, g_qh);   cudaGetSymbolAddress((void**)&gql, g_ql);
    cudaGetSymbolAddress((void**)&gkh, g_kh);   cudaGetSymbolAddress((void**)&gkl, g_kl);
    cudaGetSymbolAddress((void**)&gvh, g_vh);
    cudaGetSymbolAddress((void**)&gEh, g_Eh);
    cudaGetSymbolAddress((void**)&gFh, g_Fh);   cudaGetSymbolAddress((void**)&gFl, g_Fl);
    cudaGetSymbolAddress((void**)&gkpth, g_kpth);
    cudaGetSymbolAddress((void**)&gvph, g_vph);
    cudaGetSymbolAddress((void**)&gcath, g_cath); cudaGetSymbolAddress((void**)&gcatl, g_catl);

    cvt_split<<<MROWS * DMODEL / 256, 256>>>(x, gxh, gxl, MROWS * DMODEL);
    cvt_hi<<<1024, 256>>>(wq, gwh + 0 * 262144, 262144);
    cvt_hi<<<1024, 256>>>(wk, gwh + 1 * 262144, 262144);
    cvt_hi<<<1024, 256>>>(wv, gwh + 2 * 262144, 262144);
    cvt_hi<<<1024, 256>>>(wd, gwh + 3 * 262144, 262144);
    cvt_hi<<<HEADS * NSEQ * RRANK / 256, 256>>>(E, gEh, HEADS * NSEQ * RRANK);
    cvt_split<<<HEADS * NSEQ * RRANK / 256, 256>>>(F, gFh, gFl, HEADS * NSEQ * RRANK);

    cudaFuncSetAttribute(mma_gemm, cudaFuncAttributeMaxDynamicSharedMemorySize, GEMM_SMEM);

    dim3 gg(DMODEL / 128, MROWS / 128);
    mma_gemm<<<gg, 256, GEMM_SMEM>>>(gxh, gxl, gwh + 0 * 262144, nullptr,
                                     nullptr, gqh, gql, MROWS, DMODEL, DMODEL);
    mma_gemm<<<gg, 256, GEMM_SMEM>>>(gxh, gxl, gwh + 1 * 262144, nullptr,
                                     nullptr, gkh, gkl, MROWS, DMODEL, DMODEL);
    mma_gemm<<<gg, 256, GEMM_SMEM>>>(gxh, gxl, gwh + 2 * 262144, nullptr,
                                     nullptr, gvh, nullptr, MROWS, DMODEL, DMODEL);

    projK<<<dim3(BATCH * HEADS, NCHUNK), 256>>>(gkh, gkl, gEh, gpart);
    reduce_hi<<<1048576 / 256, 256>>>(gpart, gkpth);
    projV<<<dim3(BATCH * HEADS, NCHUNK), 256>>>(gFh, gFl, gvh, gpart);
    reduce_hi<<<1048576 / 256, 256>>>(gpart, gvph);

    cudaFuncSetAttribute(attn_mma, cudaFuncAttributeMaxDynamicSharedMemorySize, ATTN_SMEM);
    attn_mma<<<dim3(NSEQ / 128, BATCH * HEADS), 256, ATTN_SMEM>>>(
        gqh, gql, gkpth, gvph, gcath, gcatl);

    mma_gemm<<<gg, 256, GEMM_SMEM>>>(gcath, gcatl, gwh + 3 * 262144, bd,
                                     out, nullptr, nullptr, MROWS, DMODEL, DMODEL);
}